// round 1
// baseline (speedup 1.0000x reference)
#include <cuda_runtime.h>
#include <math.h>

// Problem constants
#define NB 16
#define TT 12
#define NN 325
#define D_DIM 128
#define F_DIM 256
#define H_HEADS 8
#define HD 16
#define R_TOTAL (NB*TT*NN)   // 62400

// Scratch (device globals: allocation-guard safe)
__device__ float g_q[R_TOTAL * D_DIM];
__device__ float g_k[R_TOTAL * D_DIM];
__device__ float g_v[R_TOTAL * D_DIM];
__device__ float g_att[R_TOTAL * D_DIM];
__device__ float g_h[R_TOTAL * D_DIM];
__device__ float g_mid[R_TOTAL * F_DIM];

// ---------------------------------------------------------------------------
// Shared 64x128 fp32 GEMM core: C_tile(64x128) = A(rows, KDIM) @ B(KDIM, LDB)
// block = 256 threads, thread tile 4x8. acc must be zero-initialized by caller.
// ---------------------------------------------------------------------------
template <int KDIM, int LDA, int LDB>
__device__ __forceinline__ void gemm64x128(const float* __restrict__ A,
                                           const float* __restrict__ B,
                                           int arow0, int bcol0,
                                           float (*As)[16], float (*Bs)[128],
                                           float acc[4][8]) {
    const int tid = threadIdx.x;
    const int tx = tid & 15;   // col group (8 cols)
    const int ty = tid >> 4;   // row group (4 rows)

    for (int kt = 0; kt < KDIM; kt += 16) {
        // Load A tile: 64x16 floats = 256 float4, one per thread
        {
            int r  = tid >> 2;
            int c4 = (tid & 3) << 2;
            float4 va = *(const float4*)(A + (size_t)(arow0 + r) * LDA + kt + c4);
            *(float4*)(&As[r][c4]) = va;
        }
        // Load B tile: 16x128 floats = 512 float4, two per thread
        #pragma unroll
        for (int l = 0; l < 2; l++) {
            int idx = tid + l * 256;
            int kr  = idx >> 5;
            int c4  = (idx & 31) << 2;
            float4 vb = *(const float4*)(B + (size_t)(kt + kr) * LDB + bcol0 + c4);
            *(float4*)(&Bs[kr][c4]) = vb;
        }
        __syncthreads();

        #pragma unroll
        for (int kk = 0; kk < 16; kk++) {
            float a[4], b[8];
            #pragma unroll
            for (int i = 0; i < 4; i++) a[i] = As[ty * 4 + i][kk];
            #pragma unroll
            for (int j = 0; j < 8; j++) b[j] = Bs[kk][tx * 8 + j];
            #pragma unroll
            for (int i = 0; i < 4; i++)
                #pragma unroll
                for (int j = 0; j < 8; j++)
                    acc[i][j] = fmaf(a[i], b[j], acc[i][j]);
        }
        __syncthreads();
    }
}

// ---------------------------------------------------------------------------
// Kernel 1: fused QKV projections.  grid (R/64, 3), block 256.
// ---------------------------------------------------------------------------
__global__ void qkv_kernel(const float* __restrict__ x,
                           const float* __restrict__ Wq, const float* __restrict__ bq,
                           const float* __restrict__ Wk, const float* __restrict__ bk,
                           const float* __restrict__ Wv, const float* __restrict__ bv) {
    __shared__ float As[64][16];
    __shared__ float Bs[16][128];

    const float* W;
    const float* bias;
    float* out;
    if (blockIdx.y == 0)      { W = Wq; bias = bq; out = g_q; }
    else if (blockIdx.y == 1) { W = Wk; bias = bk; out = g_k; }
    else                      { W = Wv; bias = bv; out = g_v; }

    const int row0 = blockIdx.x * 64;
    float acc[4][8];
    #pragma unroll
    for (int i = 0; i < 4; i++)
        #pragma unroll
        for (int j = 0; j < 8; j++) acc[i][j] = 0.f;

    gemm64x128<D_DIM, D_DIM, D_DIM>(x, W, row0, 0, As, Bs, acc);

    const int tx = threadIdx.x & 15;
    const int ty = threadIdx.x >> 4;
    float bv0 = bias[tx * 8 + 0], bv1 = bias[tx * 8 + 1], bv2 = bias[tx * 8 + 2], bv3 = bias[tx * 8 + 3];
    float bv4 = bias[tx * 8 + 4], bv5 = bias[tx * 8 + 5], bv6 = bias[tx * 8 + 6], bv7 = bias[tx * 8 + 7];
    #pragma unroll
    for (int i = 0; i < 4; i++) {
        int row = row0 + ty * 4 + i;
        float4 o0 = make_float4(acc[i][0] + bv0, acc[i][1] + bv1, acc[i][2] + bv2, acc[i][3] + bv3);
        float4 o1 = make_float4(acc[i][4] + bv4, acc[i][5] + bv5, acc[i][6] + bv6, acc[i][7] + bv7);
        *(float4*)(out + (size_t)row * D_DIM + tx * 8 + 0) = o0;
        *(float4*)(out + (size_t)row * D_DIM + tx * 8 + 4) = o1;
    }
}

// ---------------------------------------------------------------------------
// Kernel 2: attention per (b,h,t).  grid = B*H*T = 1536, block = 352.
// One thread per query row n; K,V head-slices in smem; single-pass softmax
// (scores are tiny for this data scale; no max subtraction needed).
// ---------------------------------------------------------------------------
__global__ void attn_kernel() {
    __shared__ float ks[NN][HD];
    __shared__ float vs[NN][HD];

    const int bid = blockIdx.x;
    const int t = bid % TT;
    const int h = (bid / TT) % H_HEADS;
    const int b = bid / (TT * H_HEADS);
    const int row0 = (b * TT + t) * NN;
    const int hoff = h * HD;
    const int tid = threadIdx.x;

    // Cooperative load of K and V slices (325 x 16 each)
    for (int idx = tid; idx < NN * 4; idx += blockDim.x) {
        int m  = idx >> 2;
        int c4 = (idx & 3) << 2;
        const float* kp = g_k + (size_t)(row0 + m) * D_DIM + hoff + c4;
        const float* vp = g_v + (size_t)(row0 + m) * D_DIM + hoff + c4;
        *(float4*)(&ks[m][c4]) = *(const float4*)kp;
        *(float4*)(&vs[m][c4]) = *(const float4*)vp;
    }
    __syncthreads();

    if (tid >= NN) return;

    float q[HD];
    const float* qp = g_q + (size_t)(row0 + tid) * D_DIM + hoff;
    #pragma unroll
    for (int c4 = 0; c4 < HD; c4 += 4)
        *(float4*)(&q[c4]) = *(const float4*)(qp + c4);

    float acc[HD];
    #pragma unroll
    for (int d = 0; d < HD; d++) acc[d] = 0.f;
    float l = 0.f;

    for (int m = 0; m < NN; m++) {
        float s = 0.f;
        #pragma unroll
        for (int d = 0; d < HD; d++) s = fmaf(q[d], ks[m][d], s);
        float p = __expf(s * 0.25f);   // /sqrt(hd)=4
        l += p;
        #pragma unroll
        for (int d = 0; d < HD; d++) acc[d] = fmaf(p, vs[m][d], acc[d]);
    }

    const float inv = 1.f / l;
    float* op = g_att + (size_t)(row0 + tid) * D_DIM + hoff;
    #pragma unroll
    for (int c4 = 0; c4 < HD; c4 += 4) {
        float4 o = make_float4(acc[c4] * inv, acc[c4 + 1] * inv, acc[c4 + 2] * inv, acc[c4 + 3] * inv);
        *(float4*)(op + c4) = o;
    }
}

// ---------------------------------------------------------------------------
// LayerNorm epilogue helper: val[4][8] holds rows (ty*4+i), cols (tx*8+j);
// 16 lanes (tx) share a row -> shfl_xor reduce within 16-lane group.
// ---------------------------------------------------------------------------
__device__ __forceinline__ void ln_write(float val[4][8], int row0,
                                         const float* __restrict__ gamma,
                                         const float* __restrict__ beta,
                                         float* __restrict__ out) {
    const int tx = threadIdx.x & 15;
    const int ty = threadIdx.x >> 4;
    #pragma unroll
    for (int i = 0; i < 4; i++) {
        float s1 = 0.f, s2 = 0.f;
        #pragma unroll
        for (int j = 0; j < 8; j++) { float v = val[i][j]; s1 += v; s2 += v * v; }
        #pragma unroll
        for (int off = 8; off >= 1; off >>= 1) {
            s1 += __shfl_xor_sync(0xffffffffu, s1, off);
            s2 += __shfl_xor_sync(0xffffffffu, s2, off);
        }
        float mean = s1 * (1.f / 128.f);
        float var  = s2 * (1.f / 128.f) - mean * mean;
        float rstd = rsqrtf(var + 1e-5f);
        int row = row0 + ty * 4 + i;
        float o[8];
        #pragma unroll
        for (int j = 0; j < 8; j++) {
            int c = tx * 8 + j;
            o[j] = (val[i][j] - mean) * rstd * gamma[c] + beta[c];
        }
        *(float4*)(out + (size_t)row * D_DIM + tx * 8 + 0) = make_float4(o[0], o[1], o[2], o[3]);
        *(float4*)(out + (size_t)row * D_DIM + tx * 8 + 4) = make_float4(o[4], o[5], o[6], o[7]);
    }
}

// ---------------------------------------------------------------------------
// Kernel 3: out = LN1(x + att @ Wo + bo)  -> g_h.  grid R/64, block 256.
// ---------------------------------------------------------------------------
__global__ void projo_ln1_kernel(const float* __restrict__ x,
                                 const float* __restrict__ Wo, const float* __restrict__ bo,
                                 const float* __restrict__ g1, const float* __restrict__ b1) {
    __shared__ float As[64][16];
    __shared__ float Bs[16][128];
    const int row0 = blockIdx.x * 64;

    float acc[4][8];
    #pragma unroll
    for (int i = 0; i < 4; i++)
        #pragma unroll
        for (int j = 0; j < 8; j++) acc[i][j] = 0.f;

    gemm64x128<D_DIM, D_DIM, D_DIM>(g_att, Wo, row0, 0, As, Bs, acc);

    const int tx = threadIdx.x & 15;
    const int ty = threadIdx.x >> 4;
    float val[4][8];
    #pragma unroll
    for (int i = 0; i < 4; i++) {
        int row = row0 + ty * 4 + i;
        const float* xp = x + (size_t)row * D_DIM + tx * 8;
        float4 x0 = *(const float4*)(xp + 0);
        float4 x1 = *(const float4*)(xp + 4);
        val[i][0] = acc[i][0] + bo[tx * 8 + 0] + x0.x;
        val[i][1] = acc[i][1] + bo[tx * 8 + 1] + x0.y;
        val[i][2] = acc[i][2] + bo[tx * 8 + 2] + x0.z;
        val[i][3] = acc[i][3] + bo[tx * 8 + 3] + x0.w;
        val[i][4] = acc[i][4] + bo[tx * 8 + 4] + x1.x;
        val[i][5] = acc[i][5] + bo[tx * 8 + 5] + x1.y;
        val[i][6] = acc[i][6] + bo[tx * 8 + 6] + x1.z;
        val[i][7] = acc[i][7] + bo[tx * 8 + 7] + x1.w;
    }
    ln_write(val, row0, g1, b1, g_h);
}

// ---------------------------------------------------------------------------
// Kernel 4: mid = gelu(h @ W1 + b1).  grid (R/64, 2), block 256.
// ---------------------------------------------------------------------------
__global__ void ffn1_kernel(const float* __restrict__ W1, const float* __restrict__ b1) {
    __shared__ float As[64][16];
    __shared__ float Bs[16][128];
    const int row0 = blockIdx.x * 64;
    const int col0 = blockIdx.y * 128;

    float acc[4][8];
    #pragma unroll
    for (int i = 0; i < 4; i++)
        #pragma unroll
        for (int j = 0; j < 8; j++) acc[i][j] = 0.f;

    gemm64x128<D_DIM, D_DIM, F_DIM>(g_h, W1, row0, col0, As, Bs, acc);

    const int tx = threadIdx.x & 15;
    const int ty = threadIdx.x >> 4;
    #pragma unroll
    for (int i = 0; i < 4; i++) {
        int row = row0 + ty * 4 + i;
        float o[8];
        #pragma unroll
        for (int j = 0; j < 8; j++) {
            int c = col0 + tx * 8 + j;
            float v = acc[i][j] + b1[c];
            o[j] = 0.5f * v * (1.f + erff(v * 0.70710678118654752f));  // exact gelu
        }
        *(float4*)(g_mid + (size_t)row * F_DIM + col0 + tx * 8 + 0) = make_float4(o[0], o[1], o[2], o[3]);
        *(float4*)(g_mid + (size_t)row * F_DIM + col0 + tx * 8 + 4) = make_float4(o[4], o[5], o[6], o[7]);
    }
}

// ---------------------------------------------------------------------------
// Kernel 5: out = LN2(h + mid @ W2 + b2).  grid R/64, block 256. Writes d_out.
// ---------------------------------------------------------------------------
__global__ void ffn2_ln2_kernel(const float* __restrict__ W2, const float* __restrict__ b2,
                                const float* __restrict__ g2, const float* __restrict__ bt2,
                                float* __restrict__ out) {
    __shared__ float As[64][16];
    __shared__ float Bs[16][128];
    const int row0 = blockIdx.x * 64;

    float acc[4][8];
    #pragma unroll
    for (int i = 0; i < 4; i++)
        #pragma unroll
        for (int j = 0; j < 8; j++) acc[i][j] = 0.f;

    gemm64x128<F_DIM, F_DIM, D_DIM>(g_mid, W2, row0, 0, As, Bs, acc);

    const int tx = threadIdx.x & 15;
    const int ty = threadIdx.x >> 4;
    float val[4][8];
    #pragma unroll
    for (int i = 0; i < 4; i++) {
        int row = row0 + ty * 4 + i;
        const float* hp = g_h + (size_t)row * D_DIM + tx * 8;
        float4 h0 = *(const float4*)(hp + 0);
        float4 h1 = *(const float4*)(hp + 4);
        val[i][0] = acc[i][0] + b2[tx * 8 + 0] + h0.x;
        val[i][1] = acc[i][1] + b2[tx * 8 + 1] + h0.y;
        val[i][2] = acc[i][2] + b2[tx * 8 + 2] + h0.z;
        val[i][3] = acc[i][3] + b2[tx * 8 + 3] + h0.w;
        val[i][4] = acc[i][4] + b2[tx * 8 + 4] + h1.x;
        val[i][5] = acc[i][5] + b2[tx * 8 + 5] + h1.y;
        val[i][6] = acc[i][6] + b2[tx * 8 + 6] + h1.z;
        val[i][7] = acc[i][7] + b2[tx * 8 + 7] + h1.w;
    }
    ln_write(val, row0, g2, bt2, out);
}

// ---------------------------------------------------------------------------
extern "C" void kernel_launch(void* const* d_in, const int* in_sizes, int n_in,
                              void* d_out, int out_size) {
    const float* x     = (const float*)d_in[0];
    const float* Wq    = (const float*)d_in[1];
    const float* bq    = (const float*)d_in[2];
    const float* Wk    = (const float*)d_in[3];
    const float* bk    = (const float*)d_in[4];
    const float* Wv    = (const float*)d_in[5];
    const float* bv    = (const float*)d_in[6];
    const float* Wo    = (const float*)d_in[7];
    const float* bo    = (const float*)d_in[8];
    const float* ln1_g = (const float*)d_in[9];
    const float* ln1_b = (const float*)d_in[10];
    const float* W1    = (const float*)d_in[11];
    const float* b1    = (const float*)d_in[12];
    const float* W2    = (const float*)d_in[13];
    const float* b2    = (const float*)d_in[14];
    const float* ln2_g = (const float*)d_in[15];
    const float* ln2_b = (const float*)d_in[16];
    float* out = (float*)d_out;

    const int nrt = R_TOTAL / 64;  // 975

    qkv_kernel<<<dim3(nrt, 3), 256>>>(x, Wq, bq, Wk, bk, Wv, bv);
    attn_kernel<<<NB * H_HEADS * TT, 352>>>();
    projo_ln1_kernel<<<nrt, 256>>>(x, Wo, bo, ln1_g, ln1_b);
    ffn1_kernel<<<dim3(nrt, 2), 256>>>(W1, b1);
    ffn2_ln2_kernel<<<nrt, 256>>>(W2, b2, ln2_g, ln2_b, out);
}

// round 3
// speedup vs baseline: 1.4628x; 1.4628x over previous
#include <cuda_runtime.h>
#include <math.h>
#include <stdint.h>

// Problem constants
#define NB 16
#define TT 12
#define NN 325
#define D_DIM 128
#define F_DIM 256
#define H_HEADS 8
#define HD 16
#define R_TOTAL (NB*TT*NN)   // 62400
#define M_TILES ((R_TOTAL + 127) / 128)   // 488

// Scratch (device globals: allocation-guard safe)
__device__ float g_q[R_TOTAL * D_DIM];
__device__ float g_k[R_TOTAL * D_DIM];
__device__ float g_v[R_TOTAL * D_DIM];
__device__ float g_att[R_TOTAL * D_DIM];
__device__ float g_h[R_TOTAL * D_DIM];
__device__ float g_mid[R_TOTAL * F_DIM];

// ---------------------------------------------------------------------------
// tf32 mma.sync GEMM: CTA tile 128x128, 8 warps (2x4), warp tile 64x32,
// K staged through SMEM in chunks of 32.
// SMEM (dynamic): As[128][36] fp32-as-tf32 at 0 (18432B),
//                 Bs[32][132] at 18432 (16896B),
//                 C  [128][130] fp32 aliased at 0 (66560B) after MMA done.
// ---------------------------------------------------------------------------
#define AS_STRIDE 36
#define BS_STRIDE 132
#define CS_STRIDE 130
#define BS_OFF (128 * AS_STRIDE)            // in floats: 4608
#define SMEM_DYN (128 * CS_STRIDE * 4)      // 66560 bytes

__device__ __forceinline__ uint32_t f2tf32(float f) {
    uint32_t r;
    asm("cvt.rna.tf32.f32 %0, %1;" : "=r"(r) : "f"(f));
    return r;
}

__device__ __forceinline__ void mma_tf32(float c[4], const uint32_t a[4], const uint32_t b[2]) {
    asm volatile(
        "mma.sync.aligned.m16n8k8.row.col.f32.tf32.tf32.f32 "
        "{%0,%1,%2,%3}, {%4,%5,%6,%7}, {%8,%9}, {%0,%1,%2,%3};"
        : "+f"(c[0]), "+f"(c[1]), "+f"(c[2]), "+f"(c[3])
        : "r"(a[0]), "r"(a[1]), "r"(a[2]), "r"(a[3]), "r"(b[0]), "r"(b[1]));
}

// Computes C(128x128) = A[row0..row0+128, :K] @ B[:K, bcol0..bcol0+128]
// into smem Cs (stride CS_STRIDE). 256 threads. A rows clamped to R_TOTAL-1.
__device__ __forceinline__ void gemm_tile(float* smf,
                                          const float* __restrict__ A, int lda, int row0,
                                          const float* __restrict__ B, int ldb, int bcol0,
                                          int K) {
    const int tid  = threadIdx.x;
    const int warp = tid >> 5;
    const int lane = tid & 31;
    const int gid  = lane >> 2;   // group id (0..7)
    const int tig  = lane & 3;    // thread in group
    const int wm   = warp >> 2;   // 0..1 -> 64-row slab
    const int wn   = warp & 3;    // 0..3 -> 32-col slab

    float acc[4][4][4];
    #pragma unroll
    for (int i = 0; i < 4; i++)
        #pragma unroll
        for (int j = 0; j < 4; j++)
            #pragma unroll
            for (int r = 0; r < 4; r++) acc[i][j][r] = 0.f;

    uint32_t* As = (uint32_t*)smf;
    uint32_t* Bs = (uint32_t*)(smf + BS_OFF);

    const int nchunk = K >> 5;
    for (int ch = 0; ch < nchunk; ch++) {
        const int kofs = ch << 5;
        // Fill A tile: 128 rows x 32 k = 1024 float4
        #pragma unroll
        for (int it = 0; it < 4; it++) {
            int idx = tid + it * 256;
            int r = idx >> 3, c4 = (idx & 7) << 2;
            int row = row0 + r;
            if (row > R_TOTAL - 1) row = R_TOTAL - 1;
            float4 v = *(const float4*)(A + (size_t)row * lda + kofs + c4);
            uint32_t* p = As + r * AS_STRIDE + c4;
            p[0] = f2tf32(v.x); p[1] = f2tf32(v.y); p[2] = f2tf32(v.z); p[3] = f2tf32(v.w);
        }
        // Fill B tile: 32 k-rows x 128 n = 1024 float4 (Bs[k][n])
        #pragma unroll
        for (int it = 0; it < 4; it++) {
            int idx = tid + it * 256;
            int k = idx >> 5, n4 = (idx & 31) << 2;
            float4 v = *(const float4*)(B + (size_t)(kofs + k) * ldb + bcol0 + n4);
            uint32_t* p = Bs + k * BS_STRIDE + n4;
            p[0] = f2tf32(v.x); p[1] = f2tf32(v.y); p[2] = f2tf32(v.z); p[3] = f2tf32(v.w);
        }
        __syncthreads();

        #pragma unroll
        for (int ks = 0; ks < 4; ks++) {
            const int k0 = ks << 3;
            uint32_t af[4][4], bf[4][2];
            #pragma unroll
            for (int mt = 0; mt < 4; mt++) {
                int row = wm * 64 + mt * 16 + gid;
                af[mt][0] = As[row * AS_STRIDE + k0 + tig];
                af[mt][1] = As[(row + 8) * AS_STRIDE + k0 + tig];
                af[mt][2] = As[row * AS_STRIDE + k0 + tig + 4];
                af[mt][3] = As[(row + 8) * AS_STRIDE + k0 + tig + 4];
            }
            #pragma unroll
            for (int nt = 0; nt < 4; nt++) {
                int n = wn * 32 + nt * 8 + gid;
                bf[nt][0] = Bs[(k0 + tig) * BS_STRIDE + n];
                bf[nt][1] = Bs[(k0 + tig + 4) * BS_STRIDE + n];
            }
            #pragma unroll
            for (int mt = 0; mt < 4; mt++)
                #pragma unroll
                for (int nt = 0; nt < 4; nt++)
                    mma_tf32(acc[mt][nt], af[mt], bf[nt]);
        }
        __syncthreads();
    }

    // Write accumulators to smem C (stride 130, float2 per c0/c1 pair)
    float* Cs = smf;
    #pragma unroll
    for (int mt = 0; mt < 4; mt++) {
        #pragma unroll
        for (int nt = 0; nt < 4; nt++) {
            int row = wm * 64 + mt * 16 + gid;
            int col = wn * 32 + nt * 8 + (tig << 1);
            *(float2*)(Cs + row * CS_STRIDE + col)       = make_float2(acc[mt][nt][0], acc[mt][nt][1]);
            *(float2*)(Cs + (row + 8) * CS_STRIDE + col) = make_float2(acc[mt][nt][2], acc[mt][nt][3]);
        }
    }
    __syncthreads();
}

// ---------------------------------------------------------------------------
// Kernel 1: QKV projections. grid (488, 3), block 256.
// ---------------------------------------------------------------------------
__global__ void __launch_bounds__(256) k_qkv(const float* __restrict__ x,
                                             const float* __restrict__ Wq, const float* __restrict__ bq,
                                             const float* __restrict__ Wk, const float* __restrict__ bk,
                                             const float* __restrict__ Wv, const float* __restrict__ bv) {
    extern __shared__ float smf[];
    const int which = blockIdx.y;
    const float* W    = (which == 0) ? Wq : (which == 1) ? Wk : Wv;
    const float* bias = (which == 0) ? bq : (which == 1) ? bk : bv;
    float* out        = (which == 0) ? g_q : (which == 1) ? g_k : g_v;
    const int row0 = blockIdx.x << 7;

    gemm_tile(smf, x, D_DIM, row0, W, D_DIM, 0, D_DIM);

    const int tid = threadIdx.x;
    if (tid < 128) {
        int row = row0 + tid;
        if (row < R_TOTAL) {
            const float* Cr = smf + tid * CS_STRIDE;
            #pragma unroll
            for (int c = 0; c < 128; c += 4) {
                float2 v0 = *(const float2*)(Cr + c);
                float2 v1 = *(const float2*)(Cr + c + 2);
                float4 o = make_float4(v0.x + bias[c], v0.y + bias[c + 1],
                                       v1.x + bias[c + 2], v1.y + bias[c + 3]);
                *(float4*)(out + (size_t)row * D_DIM + c) = o;
            }
        }
    }
}

// ---------------------------------------------------------------------------
// Kernel 2: attention per (b,h,t). grid = 1536, block = 352. Packed f32x2.
// ---------------------------------------------------------------------------
__device__ __forceinline__ unsigned long long pack2(float lo, float hi) {
    unsigned long long r;
    asm("mov.b64 %0, {%1, %2};" : "=l"(r) : "f"(lo), "f"(hi));
    return r;
}
__device__ __forceinline__ void unpack2(unsigned long long v, float& lo, float& hi) {
    asm("mov.b64 {%0, %1}, %2;" : "=f"(lo), "=f"(hi) : "l"(v));
}
__device__ __forceinline__ void ffma2(unsigned long long& d, unsigned long long a, unsigned long long b) {
    asm("fma.rn.f32x2 %0, %1, %2, %0;" : "+l"(d) : "l"(a), "l"(b));
}

__global__ void attn_kernel() {
    __shared__ float ks[NN][HD];
    __shared__ float vs[NN][HD];

    const int bid = blockIdx.x;
    const int t = bid % TT;
    const int h = (bid / TT) % H_HEADS;
    const int b = bid / (TT * H_HEADS);
    const int row0 = (b * TT + t) * NN;
    const int hoff = h * HD;
    const int tid = threadIdx.x;

    for (int idx = tid; idx < NN * 4; idx += blockDim.x) {
        int m  = idx >> 2;
        int c4 = (idx & 3) << 2;
        const float* kp = g_k + (size_t)(row0 + m) * D_DIM + hoff + c4;
        const float* vp = g_v + (size_t)(row0 + m) * D_DIM + hoff + c4;
        *(float4*)(&ks[m][c4]) = *(const float4*)kp;
        *(float4*)(&vs[m][c4]) = *(const float4*)vp;
    }
    __syncthreads();

    if (tid >= NN) return;

    unsigned long long q2[8];
    {
        const float* qp = g_q + (size_t)(row0 + tid) * D_DIM + hoff;
        #pragma unroll
        for (int i = 0; i < 8; i += 2) {
            float4 v = *(const float4*)(qp + i * 2);
            q2[i]     = pack2(v.x, v.y);
            q2[i + 1] = pack2(v.z, v.w);
        }
    }

    unsigned long long acc2[8];
    #pragma unroll
    for (int i = 0; i < 8; i++) acc2[i] = 0ull;
    float l = 0.f;

    for (int m = 0; m < NN; m++) {
        const unsigned long long* kp2 = (const unsigned long long*)(&ks[m][0]);
        unsigned long long sp0 = 0ull, sp1 = 0ull;
        #pragma unroll
        for (int i = 0; i < 8; i += 2) {
            ffma2(sp0, q2[i],     kp2[i]);
            ffma2(sp1, q2[i + 1], kp2[i + 1]);
        }
        float a0, a1, b0, b1;
        unpack2(sp0, a0, a1);
        unpack2(sp1, b0, b1);
        float s = (a0 + a1) + (b0 + b1);
        float p = __expf(s * 0.25f);
        l += p;
        unsigned long long pp = pack2(p, p);
        const unsigned long long* vp2 = (const unsigned long long*)(&vs[m][0]);
        #pragma unroll
        for (int i = 0; i < 8; i++) ffma2(acc2[i], pp, vp2[i]);
    }

    const float inv = 1.f / l;
    float* op = g_att + (size_t)(row0 + tid) * D_DIM + hoff;
    #pragma unroll
    for (int i = 0; i < 8; i += 2) {
        float x0, x1, x2, x3;
        unpack2(acc2[i], x0, x1);
        unpack2(acc2[i + 1], x2, x3);
        *(float4*)(op + i * 2) = make_float4(x0 * inv, x1 * inv, x2 * inv, x3 * inv);
    }
}

// ---------------------------------------------------------------------------
// Kernel 3: g_h = LN1(x + att @ Wo + bo). grid 488, block 256.
// ---------------------------------------------------------------------------
__global__ void __launch_bounds__(256) k_projo_ln1(const float* __restrict__ x,
                                                   const float* __restrict__ Wo, const float* __restrict__ bo,
                                                   const float* __restrict__ g1, const float* __restrict__ b1) {
    extern __shared__ float smf[];
    const int row0 = blockIdx.x << 7;
    gemm_tile(smf, g_att, D_DIM, row0, Wo, D_DIM, 0, D_DIM);

    const int tid = threadIdx.x;
    if (tid < 128) {
        int row = row0 + tid;
        if (row < R_TOTAL) {
            const float* Cr = smf + tid * CS_STRIDE;
            const float* xr = x + (size_t)row * D_DIM;
            float s1 = 0.f, s2 = 0.f;
            #pragma unroll
            for (int c = 0; c < 128; c++) {
                float v = Cr[c] + bo[c] + xr[c];
                s1 += v; s2 += v * v;
            }
            float mean = s1 * (1.f / 128.f);
            float var  = s2 * (1.f / 128.f) - mean * mean;
            float rstd = rsqrtf(var + 1e-5f);
            float* hr = g_h + (size_t)row * D_DIM;
            #pragma unroll
            for (int c = 0; c < 128; c += 4) {
                float4 o;
                o.x = (Cr[c]     + bo[c]     + xr[c]     - mean) * rstd * g1[c]     + b1[c];
                o.y = (Cr[c + 1] + bo[c + 1] + xr[c + 1] - mean) * rstd * g1[c + 1] + b1[c + 1];
                o.z = (Cr[c + 2] + bo[c + 2] + xr[c + 2] - mean) * rstd * g1[c + 2] + b1[c + 2];
                o.w = (Cr[c + 3] + bo[c + 3] + xr[c + 3] - mean) * rstd * g1[c + 3] + b1[c + 3];
                *(float4*)(hr + c) = o;
            }
        }
    }
}

// ---------------------------------------------------------------------------
// Kernel 4: g_mid = gelu(g_h @ W1 + b1). grid (488, 2), block 256.
// ---------------------------------------------------------------------------
__global__ void __launch_bounds__(256) k_ffn1(const float* __restrict__ W1,
                                              const float* __restrict__ b1) {
    extern __shared__ float smf[];
    const int row0 = blockIdx.x << 7;
    const int col0 = blockIdx.y << 7;
    gemm_tile(smf, g_h, D_DIM, row0, W1, F_DIM, col0, D_DIM);

    const int tid = threadIdx.x;
    if (tid < 128) {
        int row = row0 + tid;
        if (row < R_TOTAL) {
            const float* Cr = smf + tid * CS_STRIDE;
            #pragma unroll
            for (int c = 0; c < 128; c += 4) {
                float o[4];
                #pragma unroll
                for (int j = 0; j < 4; j++) {
                    float v = Cr[c + j] + b1[col0 + c + j];
                    o[j] = 0.5f * v * (1.f + erff(v * 0.70710678118654752f));
                }
                *(float4*)(g_mid + (size_t)row * F_DIM + col0 + c) = make_float4(o[0], o[1], o[2], o[3]);
            }
        }
    }
}

// ---------------------------------------------------------------------------
// Kernel 5: out = LN2(g_h + g_mid @ W2 + b2). grid 488, block 256. K=256.
// ---------------------------------------------------------------------------
__global__ void __launch_bounds__(256) k_ffn2_ln2(const float* __restrict__ W2,
                                                  const float* __restrict__ b2,
                                                  const float* __restrict__ g2,
                                                  const float* __restrict__ bt2,
                                                  float* __restrict__ out) {
    extern __shared__ float smf[];
    const int row0 = blockIdx.x << 7;
    gemm_tile(smf, g_mid, F_DIM, row0, W2, D_DIM, 0, F_DIM);

    const int tid = threadIdx.x;
    if (tid < 128) {
        int row = row0 + tid;
        if (row < R_TOTAL) {
            const float* Cr = smf + tid * CS_STRIDE;
            const float* hr = g_h + (size_t)row * D_DIM;
            float s1 = 0.f, s2 = 0.f;
            #pragma unroll
            for (int c = 0; c < 128; c++) {
                float v = Cr[c] + b2[c] + hr[c];
                s1 += v; s2 += v * v;
            }
            float mean = s1 * (1.f / 128.f);
            float var  = s2 * (1.f / 128.f) - mean * mean;
            float rstd = rsqrtf(var + 1e-5f);
            float* orow = out + (size_t)row * D_DIM;
            #pragma unroll
            for (int c = 0; c < 128; c += 4) {
                float4 o;
                o.x = (Cr[c]     + b2[c]     + hr[c]     - mean) * rstd * g2[c]     + bt2[c];
                o.y = (Cr[c + 1] + b2[c + 1] + hr[c + 1] - mean) * rstd * g2[c + 1] + bt2[c + 1];
                o.z = (Cr[c + 2] + b2[c + 2] + hr[c + 2] - mean) * rstd * g2[c + 2] + bt2[c + 2];
                o.w = (Cr[c + 3] + b2[c + 3] + hr[c + 3] - mean) * rstd * g2[c + 3] + bt2[c + 3];
                *(float4*)(orow + c) = o;
            }
        }
    }
}

// ---------------------------------------------------------------------------
extern "C" void kernel_launch(void* const* d_in, const int* in_sizes, int n_in,
                              void* d_out, int out_size) {
    const float* x     = (const float*)d_in[0];
    const float* Wq    = (const float*)d_in[1];
    const float* bq    = (const float*)d_in[2];
    const float* Wk    = (const float*)d_in[3];
    const float* bk    = (const float*)d_in[4];
    const float* Wv    = (const float*)d_in[5];
    const float* bv    = (const float*)d_in[6];
    const float* Wo    = (const float*)d_in[7];
    const float* bo    = (const float*)d_in[8];
    const float* ln1_g = (const float*)d_in[9];
    const float* ln1_b = (const float*)d_in[10];
    const float* W1    = (const float*)d_in[11];
    const float* b1    = (const float*)d_in[12];
    const float* W2    = (const float*)d_in[13];
    const float* b2    = (const float*)d_in[14];
    const float* ln2_g = (const float*)d_in[15];
    const float* ln2_b = (const float*)d_in[16];
    float* out = (float*)d_out;

    static bool attr_done = false;
    if (!attr_done) {
        cudaFuncSetAttribute(k_qkv,       cudaFuncAttributeMaxDynamicSharedMemorySize, SMEM_DYN);
        cudaFuncSetAttribute(k_projo_ln1, cudaFuncAttributeMaxDynamicSharedMemorySize, SMEM_DYN);
        cudaFuncSetAttribute(k_ffn1,      cudaFuncAttributeMaxDynamicSharedMemorySize, SMEM_DYN);
        cudaFuncSetAttribute(k_ffn2_ln2,  cudaFuncAttributeMaxDynamicSharedMemorySize, SMEM_DYN);
        attr_done = true;
    }

    k_qkv<<<dim3(M_TILES, 3), 256, SMEM_DYN>>>(x, Wq, bq, Wk, bk, Wv, bv);
    attn_kernel<<<NB * H_HEADS * TT, 352>>>();
    k_projo_ln1<<<M_TILES, 256, SMEM_DYN>>>(x, Wo, bo, ln1_g, ln1_b);
    k_ffn1<<<dim3(M_TILES, 2), 256, SMEM_DYN>>>(W1, b1);
    k_ffn2_ln2<<<M_TILES, 256, SMEM_DYN>>>(W2, b2, ln2_g, ln2_b, out);
}

// round 4
// speedup vs baseline: 2.5103x; 1.7161x over previous
#include <cuda_runtime.h>
#include <cuda_bf16.h>
#include <math.h>
#include <stdint.h>

// Problem constants
#define NB 16
#define TT 12
#define NN 325
#define D_DIM 128
#define F_DIM 256
#define H_HEADS 8
#define HD 16
#define R_TOTAL (NB*TT*NN)   // 62400
#define M_TILES ((R_TOTAL + 127) / 128)   // 488

// Attention padding
#define NKP 336              // keys padded to 336 (21 * 16)
#define NPAD (NKP - NN)      // 11 pad keys, each contributes exp(0)=1 to rowsum
#define VT_STRIDE 344        // bf16 elements per Vt row (pad for banks)

// Scratch (device globals: allocation-guard safe)
__device__ float g_q[R_TOTAL * D_DIM];
__device__ float g_k[R_TOTAL * D_DIM];
__device__ float g_v[R_TOTAL * D_DIM];
__device__ float g_att[R_TOTAL * D_DIM];
__device__ float g_h[R_TOTAL * D_DIM];
__device__ float g_mid[R_TOTAL * F_DIM];

// ---------------------------------------------------------------------------
// tf32 mma.sync GEMM (unchanged from R3): CTA tile 128x128, 8 warps.
// ---------------------------------------------------------------------------
#define AS_STRIDE 36
#define BS_STRIDE 132
#define CS_STRIDE 130
#define BS_OFF (128 * AS_STRIDE)
#define SMEM_DYN (128 * CS_STRIDE * 4)

__device__ __forceinline__ uint32_t f2tf32(float f) {
    uint32_t r;
    asm("cvt.rna.tf32.f32 %0, %1;" : "=r"(r) : "f"(f));
    return r;
}

__device__ __forceinline__ void mma_tf32(float c[4], const uint32_t a[4], const uint32_t b[2]) {
    asm volatile(
        "mma.sync.aligned.m16n8k8.row.col.f32.tf32.tf32.f32 "
        "{%0,%1,%2,%3}, {%4,%5,%6,%7}, {%8,%9}, {%0,%1,%2,%3};"
        : "+f"(c[0]), "+f"(c[1]), "+f"(c[2]), "+f"(c[3])
        : "r"(a[0]), "r"(a[1]), "r"(a[2]), "r"(a[3]), "r"(b[0]), "r"(b[1]));
}

__device__ __forceinline__ void gemm_tile(float* smf,
                                          const float* __restrict__ A, int lda, int row0,
                                          const float* __restrict__ B, int ldb, int bcol0,
                                          int K) {
    const int tid  = threadIdx.x;
    const int warp = tid >> 5;
    const int lane = tid & 31;
    const int gid  = lane >> 2;
    const int tig  = lane & 3;
    const int wm   = warp >> 2;
    const int wn   = warp & 3;

    float acc[4][4][4];
    #pragma unroll
    for (int i = 0; i < 4; i++)
        #pragma unroll
        for (int j = 0; j < 4; j++)
            #pragma unroll
            for (int r = 0; r < 4; r++) acc[i][j][r] = 0.f;

    uint32_t* As = (uint32_t*)smf;
    uint32_t* Bs = (uint32_t*)(smf + BS_OFF);

    const int nchunk = K >> 5;
    for (int ch = 0; ch < nchunk; ch++) {
        const int kofs = ch << 5;
        #pragma unroll
        for (int it = 0; it < 4; it++) {
            int idx = tid + it * 256;
            int r = idx >> 3, c4 = (idx & 7) << 2;
            int row = row0 + r;
            if (row > R_TOTAL - 1) row = R_TOTAL - 1;
            float4 v = *(const float4*)(A + (size_t)row * lda + kofs + c4);
            uint32_t* p = As + r * AS_STRIDE + c4;
            p[0] = f2tf32(v.x); p[1] = f2tf32(v.y); p[2] = f2tf32(v.z); p[3] = f2tf32(v.w);
        }
        #pragma unroll
        for (int it = 0; it < 4; it++) {
            int idx = tid + it * 256;
            int k = idx >> 5, n4 = (idx & 31) << 2;
            float4 v = *(const float4*)(B + (size_t)(kofs + k) * ldb + bcol0 + n4);
            uint32_t* p = Bs + k * BS_STRIDE + n4;
            p[0] = f2tf32(v.x); p[1] = f2tf32(v.y); p[2] = f2tf32(v.z); p[3] = f2tf32(v.w);
        }
        __syncthreads();

        #pragma unroll
        for (int ks = 0; ks < 4; ks++) {
            const int k0 = ks << 3;
            uint32_t af[4][4], bf[4][2];
            #pragma unroll
            for (int mt = 0; mt < 4; mt++) {
                int row = wm * 64 + mt * 16 + gid;
                af[mt][0] = As[row * AS_STRIDE + k0 + tig];
                af[mt][1] = As[(row + 8) * AS_STRIDE + k0 + tig];
                af[mt][2] = As[row * AS_STRIDE + k0 + tig + 4];
                af[mt][3] = As[(row + 8) * AS_STRIDE + k0 + tig + 4];
            }
            #pragma unroll
            for (int nt = 0; nt < 4; nt++) {
                int n = wn * 32 + nt * 8 + gid;
                bf[nt][0] = Bs[(k0 + tig) * BS_STRIDE + n];
                bf[nt][1] = Bs[(k0 + tig + 4) * BS_STRIDE + n];
            }
            #pragma unroll
            for (int mt = 0; mt < 4; mt++)
                #pragma unroll
                for (int nt = 0; nt < 4; nt++)
                    mma_tf32(acc[mt][nt], af[mt], bf[nt]);
        }
        __syncthreads();
    }

    float* Cs = smf;
    #pragma unroll
    for (int mt = 0; mt < 4; mt++) {
        #pragma unroll
        for (int nt = 0; nt < 4; nt++) {
            int row = wm * 64 + mt * 16 + gid;
            int col = wn * 32 + nt * 8 + (tig << 1);
            *(float2*)(Cs + row * CS_STRIDE + col)       = make_float2(acc[mt][nt][0], acc[mt][nt][1]);
            *(float2*)(Cs + (row + 8) * CS_STRIDE + col) = make_float2(acc[mt][nt][2], acc[mt][nt][3]);
        }
    }
    __syncthreads();
}

// ---------------------------------------------------------------------------
// Kernel 1: QKV projections. grid (488, 3), block 256.
// ---------------------------------------------------------------------------
__global__ void __launch_bounds__(256) k_qkv(const float* __restrict__ x,
                                             const float* __restrict__ Wq, const float* __restrict__ bq,
                                             const float* __restrict__ Wk, const float* __restrict__ bk,
                                             const float* __restrict__ Wv, const float* __restrict__ bv) {
    extern __shared__ float smf[];
    const int which = blockIdx.y;
    const float* W    = (which == 0) ? Wq : (which == 1) ? Wk : Wv;
    const float* bias = (which == 0) ? bq : (which == 1) ? bk : bv;
    float* out        = (which == 0) ? g_q : (which == 1) ? g_k : g_v;
    const int row0 = blockIdx.x << 7;

    gemm_tile(smf, x, D_DIM, row0, W, D_DIM, 0, D_DIM);

    const int tid = threadIdx.x;
    if (tid < 128) {
        int row = row0 + tid;
        if (row < R_TOTAL) {
            const float* Cr = smf + tid * CS_STRIDE;
            #pragma unroll
            for (int c = 0; c < 128; c += 4) {
                float2 v0 = *(const float2*)(Cr + c);
                float2 v1 = *(const float2*)(Cr + c + 2);
                float4 o = make_float4(v0.x + bias[c], v0.y + bias[c + 1],
                                       v1.x + bias[c + 2], v1.y + bias[c + 3]);
                *(float4*)(out + (size_t)row * D_DIM + c) = o;
            }
        }
    }
}

// ---------------------------------------------------------------------------
// Kernel 2: tensorized attention per (b,h,t). grid = 1536, block = 256.
// S = Q@K^T via bf16 mma (fp32 acc); P = exp(S/4) held in registers; O = P@V
// via bf16 mma. Keys padded 325->336 with zeros: pad p == exp(0) == 1 exactly,
// V pad == 0, so O is unaffected; rowsum corrected by -11.
// ---------------------------------------------------------------------------
__device__ __forceinline__ void mma_bf16(float c[4], const uint32_t a[4], const uint32_t b[2]) {
    asm volatile(
        "mma.sync.aligned.m16n8k16.row.col.f32.bf16.bf16.f32 "
        "{%0,%1,%2,%3}, {%4,%5,%6,%7}, {%8,%9}, {%0,%1,%2,%3};"
        : "+f"(c[0]), "+f"(c[1]), "+f"(c[2]), "+f"(c[3])
        : "r"(a[0]), "r"(a[1]), "r"(a[2]), "r"(a[3]), "r"(b[0]), "r"(b[1]));
}

// pack {lo=x, hi=y} as bf16x2 (PTX cvt writes first operand to hi half)
__device__ __forceinline__ uint32_t packbf(float x, float y) {
    uint32_t r;
    asm("cvt.rn.bf16x2.f32 %0, %1, %2;" : "=r"(r) : "f"(y), "f"(x));
    return r;
}

__global__ void __launch_bounds__(256) attn_kernel() {
    __shared__ __align__(16) uint32_t Qs[NKP * 8];        // [336][16] bf16, 8 u32/row
    __shared__ __align__(16) uint32_t Ks[NKP * 8];
    __shared__ __align__(16) uint32_t Vt[HD * (VT_STRIDE / 2)];  // [16][344] bf16

    const int bid = blockIdx.x;
    const int t = bid % TT;
    const int h = (bid / TT) % H_HEADS;
    const int b = bid / (TT * H_HEADS);
    const int row0 = (b * TT + t) * NN;
    const int hoff = h * HD;
    const int tid = threadIdx.x;

    __nv_bfloat16* Vtb = (__nv_bfloat16*)Vt;

    // Fill: 336 key-rows x 4 float4-groups
    for (int idx = tid; idx < NKP * 4; idx += 256) {
        int m = idx >> 2;
        int c4 = (idx & 3) << 2;
        float4 qv, kv, vv;
        if (m < NN) {
            size_t base = (size_t)(row0 + m) * D_DIM + hoff + c4;
            qv = *(const float4*)(g_q + base);
            kv = *(const float4*)(g_k + base);
            vv = *(const float4*)(g_v + base);
        } else {
            qv = kv = vv = make_float4(0.f, 0.f, 0.f, 0.f);
        }
        uint32_t* qp = Qs + m * 8 + (c4 >> 1);
        qp[0] = packbf(qv.x, qv.y);
        qp[1] = packbf(qv.z, qv.w);
        uint32_t* kp = Ks + m * 8 + (c4 >> 1);
        kp[0] = packbf(kv.x, kv.y);
        kp[1] = packbf(kv.z, kv.w);
        Vtb[(c4 + 0) * VT_STRIDE + m] = __float2bfloat16(vv.x);
        Vtb[(c4 + 1) * VT_STRIDE + m] = __float2bfloat16(vv.y);
        Vtb[(c4 + 2) * VT_STRIDE + m] = __float2bfloat16(vv.z);
        Vtb[(c4 + 3) * VT_STRIDE + m] = __float2bfloat16(vv.w);
    }
    __syncthreads();

    const int warp = tid >> 5;
    const int lane = tid & 31;
    const int gid  = lane >> 2;
    const int tig  = lane & 3;

    // m-tiles (16 rows each): 21 tiles over 8 warps
    for (int mt = warp; mt < 21; mt += 8) {
        const int m0 = mt << 4;
        uint32_t qa[4];
        qa[0] = Qs[(m0 + gid) * 8 + tig];
        qa[1] = Qs[(m0 + gid + 8) * 8 + tig];
        qa[2] = Qs[(m0 + gid) * 8 + tig + 4];
        qa[3] = Qs[(m0 + gid + 8) * 8 + tig + 4];

        float oc0[4] = {0.f, 0.f, 0.f, 0.f};
        float oc1[4] = {0.f, 0.f, 0.f, 0.f};
        float rs0 = 0.f, rs1 = 0.f;

        for (int j = 0; j < 21; j++) {
            // two S tiles: cols 16j..16j+7 and 16j+8..16j+15
            float c0[4] = {0.f, 0.f, 0.f, 0.f};
            float c1[4] = {0.f, 0.f, 0.f, 0.f};
            {
                int nr = (j << 4) + gid;
                uint32_t kb[2];
                kb[0] = Ks[nr * 8 + tig];
                kb[1] = Ks[nr * 8 + tig + 4];
                mma_bf16(c0, qa, kb);
                kb[0] = Ks[(nr + 8) * 8 + tig];
                kb[1] = Ks[(nr + 8) * 8 + tig + 4];
                mma_bf16(c1, qa, kb);
            }
            float p00 = __expf(c0[0] * 0.25f);
            float p01 = __expf(c0[1] * 0.25f);
            float p02 = __expf(c0[2] * 0.25f);
            float p03 = __expf(c0[3] * 0.25f);
            float p10 = __expf(c1[0] * 0.25f);
            float p11 = __expf(c1[1] * 0.25f);
            float p12 = __expf(c1[2] * 0.25f);
            float p13 = __expf(c1[3] * 0.25f);
            rs0 += (p00 + p01) + (p10 + p11);
            rs1 += (p02 + p03) + (p12 + p13);

            uint32_t pa[4];
            pa[0] = packbf(p00, p01);   // row gid,   k 16j+2tig
            pa[1] = packbf(p02, p03);   // row gid+8, k 16j+2tig
            pa[2] = packbf(p10, p11);   // row gid,   k 16j+8+2tig
            pa[3] = packbf(p12, p13);   // row gid+8, k 16j+8+2tig

            const int kb0 = (j << 3);   // uint32 index of key 16j
            uint32_t vb[2];
            vb[0] = Vt[(gid)     * (VT_STRIDE / 2) + kb0 + tig];
            vb[1] = Vt[(gid)     * (VT_STRIDE / 2) + kb0 + tig + 4];
            mma_bf16(oc0, pa, vb);
            vb[0] = Vt[(gid + 8) * (VT_STRIDE / 2) + kb0 + tig];
            vb[1] = Vt[(gid + 8) * (VT_STRIDE / 2) + kb0 + tig + 4];
            mma_bf16(oc1, pa, vb);
        }

        // reduce rowsums across the 4 tig lanes
        rs0 += __shfl_xor_sync(0xffffffffu, rs0, 1);
        rs0 += __shfl_xor_sync(0xffffffffu, rs0, 2);
        rs1 += __shfl_xor_sync(0xffffffffu, rs1, 1);
        rs1 += __shfl_xor_sync(0xffffffffu, rs1, 2);
        float i0 = 1.f / (rs0 - (float)NPAD);
        float i1 = 1.f / (rs1 - (float)NPAD);

        int r0 = m0 + gid;
        int r1 = m0 + gid + 8;
        if (r0 < NN) {
            float* op = g_att + (size_t)(row0 + r0) * D_DIM + hoff;
            *(float2*)(op + 2 * tig)     = make_float2(oc0[0] * i0, oc0[1] * i0);
            *(float2*)(op + 8 + 2 * tig) = make_float2(oc1[0] * i0, oc1[1] * i0);
        }
        if (r1 < NN) {
            float* op = g_att + (size_t)(row0 + r1) * D_DIM + hoff;
            *(float2*)(op + 2 * tig)     = make_float2(oc0[2] * i1, oc0[3] * i1);
            *(float2*)(op + 8 + 2 * tig) = make_float2(oc1[2] * i1, oc1[3] * i1);
        }
    }
}

// ---------------------------------------------------------------------------
// Kernel 3: g_h = LN1(x + att @ Wo + bo). grid 488, block 256.
// ---------------------------------------------------------------------------
__global__ void __launch_bounds__(256) k_projo_ln1(const float* __restrict__ x,
                                                   const float* __restrict__ Wo, const float* __restrict__ bo,
                                                   const float* __restrict__ g1, const float* __restrict__ b1) {
    extern __shared__ float smf[];
    const int row0 = blockIdx.x << 7;
    gemm_tile(smf, g_att, D_DIM, row0, Wo, D_DIM, 0, D_DIM);

    const int tid = threadIdx.x;
    if (tid < 128) {
        int row = row0 + tid;
        if (row < R_TOTAL) {
            const float* Cr = smf + tid * CS_STRIDE;
            const float* xr = x + (size_t)row * D_DIM;
            float s1 = 0.f, s2 = 0.f;
            #pragma unroll
            for (int c = 0; c < 128; c++) {
                float v = Cr[c] + bo[c] + xr[c];
                s1 += v; s2 += v * v;
            }
            float mean = s1 * (1.f / 128.f);
            float var  = s2 * (1.f / 128.f) - mean * mean;
            float rstd = rsqrtf(var + 1e-5f);
            float* hr = g_h + (size_t)row * D_DIM;
            #pragma unroll
            for (int c = 0; c < 128; c += 4) {
                float4 o;
                o.x = (Cr[c]     + bo[c]     + xr[c]     - mean) * rstd * g1[c]     + b1[c];
                o.y = (Cr[c + 1] + bo[c + 1] + xr[c + 1] - mean) * rstd * g1[c + 1] + b1[c + 1];
                o.z = (Cr[c + 2] + bo[c + 2] + xr[c + 2] - mean) * rstd * g1[c + 2] + b1[c + 2];
                o.w = (Cr[c + 3] + bo[c + 3] + xr[c + 3] - mean) * rstd * g1[c + 3] + b1[c + 3];
                *(float4*)(hr + c) = o;
            }
        }
    }
}

// ---------------------------------------------------------------------------
// Kernel 4: g_mid = gelu(g_h @ W1 + b1). grid (488, 2), block 256.
// ---------------------------------------------------------------------------
__global__ void __launch_bounds__(256) k_ffn1(const float* __restrict__ W1,
                                              const float* __restrict__ b1) {
    extern __shared__ float smf[];
    const int row0 = blockIdx.x << 7;
    const int col0 = blockIdx.y << 7;
    gemm_tile(smf, g_h, D_DIM, row0, W1, F_DIM, col0, D_DIM);

    const int tid = threadIdx.x;
    if (tid < 128) {
        int row = row0 + tid;
        if (row < R_TOTAL) {
            const float* Cr = smf + tid * CS_STRIDE;
            #pragma unroll
            for (int c = 0; c < 128; c += 4) {
                float o[4];
                #pragma unroll
                for (int j = 0; j < 4; j++) {
                    float v = Cr[c + j] + b1[col0 + c + j];
                    o[j] = 0.5f * v * (1.f + erff(v * 0.70710678118654752f));
                }
                *(float4*)(g_mid + (size_t)row * F_DIM + col0 + c) = make_float4(o[0], o[1], o[2], o[3]);
            }
        }
    }
}

// ---------------------------------------------------------------------------
// Kernel 5: out = LN2(g_h + g_mid @ W2 + b2). grid 488, block 256. K=256.
// ---------------------------------------------------------------------------
__global__ void __launch_bounds__(256) k_ffn2_ln2(const float* __restrict__ W2,
                                                  const float* __restrict__ b2,
                                                  const float* __restrict__ g2,
                                                  const float* __restrict__ bt2,
                                                  float* __restrict__ out) {
    extern __shared__ float smf[];
    const int row0 = blockIdx.x << 7;
    gemm_tile(smf, g_mid, F_DIM, row0, W2, D_DIM, 0, F_DIM);

    const int tid = threadIdx.x;
    if (tid < 128) {
        int row = row0 + tid;
        if (row < R_TOTAL) {
            const float* Cr = smf + tid * CS_STRIDE;
            const float* hr = g_h + (size_t)row * D_DIM;
            float s1 = 0.f, s2 = 0.f;
            #pragma unroll
            for (int c = 0; c < 128; c++) {
                float v = Cr[c] + b2[c] + hr[c];
                s1 += v; s2 += v * v;
            }
            float mean = s1 * (1.f / 128.f);
            float var  = s2 * (1.f / 128.f) - mean * mean;
            float rstd = rsqrtf(var + 1e-5f);
            float* orow = out + (size_t)row * D_DIM;
            #pragma unroll
            for (int c = 0; c < 128; c += 4) {
                float4 o;
                o.x = (Cr[c]     + b2[c]     + hr[c]     - mean) * rstd * g2[c]     + bt2[c];
                o.y = (Cr[c + 1] + b2[c + 1] + hr[c + 1] - mean) * rstd * g2[c + 1] + bt2[c + 1];
                o.z = (Cr[c + 2] + b2[c + 2] + hr[c + 2] - mean) * rstd * g2[c + 2] + bt2[c + 2];
                o.w = (Cr[c + 3] + b2[c + 3] + hr[c + 3] - mean) * rstd * g2[c + 3] + bt2[c + 3];
                *(float4*)(orow + c) = o;
            }
        }
    }
}

// ---------------------------------------------------------------------------
extern "C" void kernel_launch(void* const* d_in, const int* in_sizes, int n_in,
                              void* d_out, int out_size) {
    const float* x     = (const float*)d_in[0];
    const float* Wq    = (const float*)d_in[1];
    const float* bq    = (const float*)d_in[2];
    const float* Wk    = (const float*)d_in[3];
    const float* bk    = (const float*)d_in[4];
    const float* Wv    = (const float*)d_in[5];
    const float* bv    = (const float*)d_in[6];
    const float* Wo    = (const float*)d_in[7];
    const float* bo    = (const float*)d_in[8];
    const float* ln1_g = (const float*)d_in[9];
    const float* ln1_b = (const float*)d_in[10];
    const float* W1    = (const float*)d_in[11];
    const float* b1    = (const float*)d_in[12];
    const float* W2    = (const float*)d_in[13];
    const float* b2    = (const float*)d_in[14];
    const float* ln2_g = (const float*)d_in[15];
    const float* ln2_b = (const float*)d_in[16];
    float* out = (float*)d_out;

    cudaFuncSetAttribute(k_qkv,       cudaFuncAttributeMaxDynamicSharedMemorySize, SMEM_DYN);
    cudaFuncSetAttribute(k_projo_ln1, cudaFuncAttributeMaxDynamicSharedMemorySize, SMEM_DYN);
    cudaFuncSetAttribute(k_ffn1,      cudaFuncAttributeMaxDynamicSharedMemorySize, SMEM_DYN);
    cudaFuncSetAttribute(k_ffn2_ln2,  cudaFuncAttributeMaxDynamicSharedMemorySize, SMEM_DYN);

    k_qkv<<<dim3(M_TILES, 3), 256, SMEM_DYN>>>(x, Wq, bq, Wk, bk, Wv, bv);
    attn_kernel<<<NB * H_HEADS * TT, 256>>>();
    k_projo_ln1<<<M_TILES, 256, SMEM_DYN>>>(x, Wo, bo, ln1_g, ln1_b);
    k_ffn1<<<dim3(M_TILES, 2), 256, SMEM_DYN>>>(W1, b1);
    k_ffn2_ln2<<<M_TILES, 256, SMEM_DYN>>>(W2, b2, ln2_g, ln2_b, out);
}

// round 5
// speedup vs baseline: 3.1731x; 1.2641x over previous
#include <cuda_runtime.h>
#include <cuda_bf16.h>
#include <math.h>
#include <stdint.h>

// Problem constants
#define NB 16
#define TT 12
#define NN 325
#define D_DIM 128
#define F_DIM 256
#define H_HEADS 8
#define HD 16
#define R_TOTAL (NB*TT*NN)   // 62400
#define M_TILES ((R_TOTAL + 127) / 128)   // 488

// Attention padding
#define NKP 336
#define NPAD (NKP - NN)
#define VT_STRIDE 344

// Scratch (device globals: allocation-guard safe)
__device__ float g_q[R_TOTAL * D_DIM];
__device__ float g_k[R_TOTAL * D_DIM];
__device__ float g_v[R_TOTAL * D_DIM];
__device__ float g_att[R_TOTAL * D_DIM];
__device__ float g_h[R_TOTAL * D_DIM];
__device__ float g_mid[R_TOTAL * F_DIM];

// ---------------------------------------------------------------------------
// bf16 mma.sync GEMM: CTA tile 128x128, 8 warps (2x4), warp tile 64x32,
// K staged in chunks of 32 through smem; ldmatrix fragment loads.
// As: [128 rows][20 u32] (u32 = 2 bf16 along k), rows pad->conflict-free ldsm.
// Bs: [32 k-rows][68 u32] (u32 = 2 bf16 along n).
// ---------------------------------------------------------------------------
#define AS_U32 20
#define BS_U32 68
#define AS_BYTES (128 * AS_U32 * 4)          // 10240
#define BS_BYTES (32 * BS_U32 * 4)           // 8704
#define TILE_SMEM (AS_BYTES + BS_BYTES)      // 18944
#define CS_STRIDE 130
#define LN_SMEM (128 * CS_STRIDE * 4)        // 66560

// pack {lo=x, hi=y} as bf16x2
__device__ __forceinline__ uint32_t packbf(float x, float y) {
    uint32_t r;
    asm("cvt.rn.bf16x2.f32 %0, %1, %2;" : "=r"(r) : "f"(y), "f"(x));
    return r;
}

__device__ __forceinline__ void mma_bf16(float c[4], const uint32_t a[4], const uint32_t b[2]) {
    asm volatile(
        "mma.sync.aligned.m16n8k16.row.col.f32.bf16.bf16.f32 "
        "{%0,%1,%2,%3}, {%4,%5,%6,%7}, {%8,%9}, {%0,%1,%2,%3};"
        : "+f"(c[0]), "+f"(c[1]), "+f"(c[2]), "+f"(c[3])
        : "r"(a[0]), "r"(a[1]), "r"(a[2]), "r"(a[3]), "r"(b[0]), "r"(b[1]));
}

__device__ __forceinline__ void ldsm_x4(uint32_t r[4], uint32_t addr) {
    asm volatile("ldmatrix.sync.aligned.m8n8.x4.shared.b16 {%0,%1,%2,%3}, [%4];"
        : "=r"(r[0]), "=r"(r[1]), "=r"(r[2]), "=r"(r[3]) : "r"(addr));
}
__device__ __forceinline__ void ldsm_x2t(uint32_t r[2], uint32_t addr) {
    asm volatile("ldmatrix.sync.aligned.m8n8.x2.trans.shared.b16 {%0,%1}, [%2];"
        : "=r"(r[0]), "=r"(r[1]) : "r"(addr));
}

// Mainloop: acc[mt][nt][4] = A[row0.., :K] @ B[:K, bcol0..], bf16 inputs.
__device__ __forceinline__ void gemm_bf16(char* sm,
                                          const float* __restrict__ A, int lda, int row0,
                                          const float* __restrict__ B, int ldb, int bcol0,
                                          int K, float acc[4][4][4]) {
    const int tid  = threadIdx.x;
    const int warp = tid >> 5;
    const int lane = tid & 31;
    const int wm   = warp >> 2;
    const int wn   = warp & 3;

    uint32_t* As = (uint32_t*)sm;
    uint32_t* Bs = (uint32_t*)(sm + AS_BYTES);
    const uint32_t smA = (uint32_t)__cvta_generic_to_shared(As);
    const uint32_t smB = (uint32_t)__cvta_generic_to_shared(Bs);
    const uint32_t aBase = smA + (uint32_t)(wm * 64 + (lane & 15)) * (AS_U32 * 4)
                         + ((uint32_t)(lane >> 4) << 4);
    const uint32_t bBase = smB + (uint32_t)(lane & 15) * (BS_U32 * 4) + (uint32_t)wn * 64;

    #pragma unroll
    for (int i = 0; i < 4; i++)
        #pragma unroll
        for (int j = 0; j < 4; j++)
            #pragma unroll
            for (int r = 0; r < 4; r++) acc[i][j][r] = 0.f;

    const int nchunk = K >> 5;
    for (int ch = 0; ch < nchunk; ch++) {
        const int kofs = ch << 5;
        // Fill A: 128 rows x 32 k
        #pragma unroll
        for (int it = 0; it < 4; it++) {
            int idx = tid + it * 256;
            int r = idx >> 3, c4 = (idx & 7) << 2;
            int row = row0 + r;
            if (row > R_TOTAL - 1) row = R_TOTAL - 1;
            float4 v = *(const float4*)(A + (size_t)row * lda + kofs + c4);
            uint32_t* p = As + r * AS_U32 + (c4 >> 1);
            p[0] = packbf(v.x, v.y);
            p[1] = packbf(v.z, v.w);
        }
        // Fill B: 32 k-rows x 128 n
        #pragma unroll
        for (int it = 0; it < 4; it++) {
            int idx = tid + it * 256;
            int k = idx >> 5, n4 = (idx & 31) << 2;
            float4 v = *(const float4*)(B + (size_t)(kofs + k) * ldb + bcol0 + n4);
            uint32_t* p = Bs + k * BS_U32 + (n4 >> 1);
            p[0] = packbf(v.x, v.y);
            p[1] = packbf(v.z, v.w);
        }
        __syncthreads();

        #pragma unroll
        for (int ks = 0; ks < 2; ks++) {
            uint32_t af[4][4], bfr[4][2];
            #pragma unroll
            for (int mt = 0; mt < 4; mt++)
                ldsm_x4(af[mt], aBase + mt * (16 * AS_U32 * 4) + ks * 32);
            #pragma unroll
            for (int nt = 0; nt < 4; nt++)
                ldsm_x2t(bfr[nt], bBase + ks * (16 * BS_U32 * 4) + nt * 16);
            #pragma unroll
            for (int mt = 0; mt < 4; mt++)
                #pragma unroll
                for (int nt = 0; nt < 4; nt++)
                    mma_bf16(acc[mt][nt], af[mt], bfr[nt]);
        }
        __syncthreads();
    }
}

// Stage accumulators to smem C[128][130] for row-wise epilogues.
__device__ __forceinline__ void stage_c(float* smf, float acc[4][4][4]) {
    const int tid  = threadIdx.x;
    const int warp = tid >> 5;
    const int lane = tid & 31;
    const int gid  = lane >> 2;
    const int tig  = lane & 3;
    const int wm   = warp >> 2;
    const int wn   = warp & 3;
    #pragma unroll
    for (int mt = 0; mt < 4; mt++) {
        #pragma unroll
        for (int nt = 0; nt < 4; nt++) {
            int row = wm * 64 + mt * 16 + gid;
            int col = wn * 32 + nt * 8 + (tig << 1);
            *(float2*)(smf + row * CS_STRIDE + col)       = make_float2(acc[mt][nt][0], acc[mt][nt][1]);
            *(float2*)(smf + (row + 8) * CS_STRIDE + col) = make_float2(acc[mt][nt][2], acc[mt][nt][3]);
        }
    }
    __syncthreads();
}

// ---------------------------------------------------------------------------
// Kernel 1: QKV projections, direct fragment store. grid (488, 3), block 256.
// ---------------------------------------------------------------------------
__global__ void __launch_bounds__(256) k_qkv(const float* __restrict__ x,
                                             const float* __restrict__ Wq, const float* __restrict__ bq,
                                             const float* __restrict__ Wk, const float* __restrict__ bk,
                                             const float* __restrict__ Wv, const float* __restrict__ bv) {
    extern __shared__ char sm[];
    const int which = blockIdx.y;
    const float* W    = (which == 0) ? Wq : (which == 1) ? Wk : Wv;
    const float* bias = (which == 0) ? bq : (which == 1) ? bk : bv;
    float* out        = (which == 0) ? g_q : (which == 1) ? g_k : g_v;
    const int row0 = blockIdx.x << 7;

    float acc[4][4][4];
    gemm_bf16(sm, x, D_DIM, row0, W, D_DIM, 0, D_DIM, acc);

    const int tid  = threadIdx.x;
    const int warp = tid >> 5;
    const int lane = tid & 31;
    const int gid  = lane >> 2;
    const int tig  = lane & 3;
    const int wm   = warp >> 2;
    const int wn   = warp & 3;

    #pragma unroll
    for (int mt = 0; mt < 4; mt++) {
        int r0 = row0 + wm * 64 + mt * 16 + gid;
        int r1 = r0 + 8;
        #pragma unroll
        for (int nt = 0; nt < 4; nt++) {
            int col = wn * 32 + nt * 8 + (tig << 1);
            float b0 = bias[col], b1 = bias[col + 1];
            if (r0 < R_TOTAL)
                *(float2*)(out + (size_t)r0 * D_DIM + col) = make_float2(acc[mt][nt][0] + b0, acc[mt][nt][1] + b1);
            if (r1 < R_TOTAL)
                *(float2*)(out + (size_t)r1 * D_DIM + col) = make_float2(acc[mt][nt][2] + b0, acc[mt][nt][3] + b1);
        }
    }
}

// ---------------------------------------------------------------------------
// Kernel 2: tensorized attention per (b,h,t). grid = 1536, block = 256.
// ---------------------------------------------------------------------------
__global__ void __launch_bounds__(256) attn_kernel() {
    __shared__ __align__(16) uint32_t Qs[NKP * 8];
    __shared__ __align__(16) uint32_t Ks[NKP * 8];
    __shared__ __align__(16) uint32_t Vt[HD * (VT_STRIDE / 2)];

    const int bid = blockIdx.x;
    const int t = bid % TT;
    const int h = (bid / TT) % H_HEADS;
    const int b = bid / (TT * H_HEADS);
    const int row0 = (b * TT + t) * NN;
    const int hoff = h * HD;
    const int tid = threadIdx.x;

    __nv_bfloat16* Vtb = (__nv_bfloat16*)Vt;

    for (int idx = tid; idx < NKP * 4; idx += 256) {
        int m = idx >> 2;
        int c4 = (idx & 3) << 2;
        float4 qv, kv, vv;
        if (m < NN) {
            size_t base = (size_t)(row0 + m) * D_DIM + hoff + c4;
            qv = *(const float4*)(g_q + base);
            kv = *(const float4*)(g_k + base);
            vv = *(const float4*)(g_v + base);
        } else {
            qv = kv = vv = make_float4(0.f, 0.f, 0.f, 0.f);
        }
        uint32_t* qp = Qs + m * 8 + (c4 >> 1);
        qp[0] = packbf(qv.x, qv.y);
        qp[1] = packbf(qv.z, qv.w);
        uint32_t* kp = Ks + m * 8 + (c4 >> 1);
        kp[0] = packbf(kv.x, kv.y);
        kp[1] = packbf(kv.z, kv.w);
        Vtb[(c4 + 0) * VT_STRIDE + m] = __float2bfloat16(vv.x);
        Vtb[(c4 + 1) * VT_STRIDE + m] = __float2bfloat16(vv.y);
        Vtb[(c4 + 2) * VT_STRIDE + m] = __float2bfloat16(vv.z);
        Vtb[(c4 + 3) * VT_STRIDE + m] = __float2bfloat16(vv.w);
    }
    __syncthreads();

    const int warp = tid >> 5;
    const int lane = tid & 31;
    const int gid  = lane >> 2;
    const int tig  = lane & 3;

    for (int mt = warp; mt < 21; mt += 8) {
        const int m0 = mt << 4;
        uint32_t qa[4];
        qa[0] = Qs[(m0 + gid) * 8 + tig];
        qa[1] = Qs[(m0 + gid + 8) * 8 + tig];
        qa[2] = Qs[(m0 + gid) * 8 + tig + 4];
        qa[3] = Qs[(m0 + gid + 8) * 8 + tig + 4];

        float oc0[4] = {0.f, 0.f, 0.f, 0.f};
        float oc1[4] = {0.f, 0.f, 0.f, 0.f};
        float rs0 = 0.f, rs1 = 0.f;

        for (int j = 0; j < 21; j++) {
            float c0[4] = {0.f, 0.f, 0.f, 0.f};
            float c1[4] = {0.f, 0.f, 0.f, 0.f};
            {
                int nr = (j << 4) + gid;
                uint32_t kb[2];
                kb[0] = Ks[nr * 8 + tig];
                kb[1] = Ks[nr * 8 + tig + 4];
                mma_bf16(c0, qa, kb);
                kb[0] = Ks[(nr + 8) * 8 + tig];
                kb[1] = Ks[(nr + 8) * 8 + tig + 4];
                mma_bf16(c1, qa, kb);
            }
            float p00 = __expf(c0[0] * 0.25f);
            float p01 = __expf(c0[1] * 0.25f);
            float p02 = __expf(c0[2] * 0.25f);
            float p03 = __expf(c0[3] * 0.25f);
            float p10 = __expf(c1[0] * 0.25f);
            float p11 = __expf(c1[1] * 0.25f);
            float p12 = __expf(c1[2] * 0.25f);
            float p13 = __expf(c1[3] * 0.25f);
            rs0 += (p00 + p01) + (p10 + p11);
            rs1 += (p02 + p03) + (p12 + p13);

            uint32_t pa[4];
            pa[0] = packbf(p00, p01);
            pa[1] = packbf(p02, p03);
            pa[2] = packbf(p10, p11);
            pa[3] = packbf(p12, p13);

            const int kb0 = (j << 3);
            uint32_t vb[2];
            vb[0] = Vt[(gid)     * (VT_STRIDE / 2) + kb0 + tig];
            vb[1] = Vt[(gid)     * (VT_STRIDE / 2) + kb0 + tig + 4];
            mma_bf16(oc0, pa, vb);
            vb[0] = Vt[(gid + 8) * (VT_STRIDE / 2) + kb0 + tig];
            vb[1] = Vt[(gid + 8) * (VT_STRIDE / 2) + kb0 + tig + 4];
            mma_bf16(oc1, pa, vb);
        }

        rs0 += __shfl_xor_sync(0xffffffffu, rs0, 1);
        rs0 += __shfl_xor_sync(0xffffffffu, rs0, 2);
        rs1 += __shfl_xor_sync(0xffffffffu, rs1, 1);
        rs1 += __shfl_xor_sync(0xffffffffu, rs1, 2);
        float i0 = 1.f / (rs0 - (float)NPAD);
        float i1 = 1.f / (rs1 - (float)NPAD);

        int r0 = m0 + gid;
        int r1 = m0 + gid + 8;
        if (r0 < NN) {
            float* op = g_att + (size_t)(row0 + r0) * D_DIM + hoff;
            *(float2*)(op + 2 * tig)     = make_float2(oc0[0] * i0, oc0[1] * i0);
            *(float2*)(op + 8 + 2 * tig) = make_float2(oc1[0] * i0, oc1[1] * i0);
        }
        if (r1 < NN) {
            float* op = g_att + (size_t)(row0 + r1) * D_DIM + hoff;
            *(float2*)(op + 2 * tig)     = make_float2(oc0[2] * i1, oc0[3] * i1);
            *(float2*)(op + 8 + 2 * tig) = make_float2(oc1[2] * i1, oc1[3] * i1);
        }
    }
}

// ---------------------------------------------------------------------------
// Kernel 3: g_h = LN1(x + att @ Wo + bo). grid 488, block 256.
// ---------------------------------------------------------------------------
__global__ void __launch_bounds__(256) k_projo_ln1(const float* __restrict__ x,
                                                   const float* __restrict__ Wo, const float* __restrict__ bo,
                                                   const float* __restrict__ g1, const float* __restrict__ b1) {
    extern __shared__ char sm[];
    float* smf = (float*)sm;
    const int row0 = blockIdx.x << 7;

    float acc[4][4][4];
    gemm_bf16(sm, g_att, D_DIM, row0, Wo, D_DIM, 0, D_DIM, acc);
    stage_c(smf, acc);

    const int tid = threadIdx.x;
    if (tid < 128) {
        int row = row0 + tid;
        if (row < R_TOTAL) {
            const float* Cr = smf + tid * CS_STRIDE;
            const float* xr = x + (size_t)row * D_DIM;
            float s1 = 0.f, s2 = 0.f;
            #pragma unroll
            for (int c = 0; c < 128; c++) {
                float v = Cr[c] + bo[c] + xr[c];
                s1 += v; s2 += v * v;
            }
            float mean = s1 * (1.f / 128.f);
            float var  = s2 * (1.f / 128.f) - mean * mean;
            float rstd = rsqrtf(var + 1e-5f);
            float* hr = g_h + (size_t)row * D_DIM;
            #pragma unroll
            for (int c = 0; c < 128; c += 4) {
                float4 o;
                o.x = (Cr[c]     + bo[c]     + xr[c]     - mean) * rstd * g1[c]     + b1[c];
                o.y = (Cr[c + 1] + bo[c + 1] + xr[c + 1] - mean) * rstd * g1[c + 1] + b1[c + 1];
                o.z = (Cr[c + 2] + bo[c + 2] + xr[c + 2] - mean) * rstd * g1[c + 2] + b1[c + 2];
                o.w = (Cr[c + 3] + bo[c + 3] + xr[c + 3] - mean) * rstd * g1[c + 3] + b1[c + 3];
                *(float4*)(hr + c) = o;
            }
        }
    }
}

// ---------------------------------------------------------------------------
// Kernel 4: g_mid = gelu(g_h @ W1 + b1), direct store. grid (488, 2), block 256.
// ---------------------------------------------------------------------------
__global__ void __launch_bounds__(256) k_ffn1(const float* __restrict__ W1,
                                              const float* __restrict__ b1) {
    extern __shared__ char sm[];
    const int row0 = blockIdx.x << 7;
    const int col0 = blockIdx.y << 7;

    float acc[4][4][4];
    gemm_bf16(sm, g_h, D_DIM, row0, W1, F_DIM, col0, D_DIM, acc);

    const int tid  = threadIdx.x;
    const int warp = tid >> 5;
    const int lane = tid & 31;
    const int gid  = lane >> 2;
    const int tig  = lane & 3;
    const int wm   = warp >> 2;
    const int wn   = warp & 3;

    #pragma unroll
    for (int mt = 0; mt < 4; mt++) {
        int r0 = row0 + wm * 64 + mt * 16 + gid;
        int r1 = r0 + 8;
        #pragma unroll
        for (int nt = 0; nt < 4; nt++) {
            int col = col0 + wn * 32 + nt * 8 + (tig << 1);
            float b0 = b1[col], bb1 = b1[col + 1];
            float v0 = acc[mt][nt][0] + b0;
            float v1 = acc[mt][nt][1] + bb1;
            float v2 = acc[mt][nt][2] + b0;
            float v3 = acc[mt][nt][3] + bb1;
            float g0 = 0.5f * v0 * (1.f + erff(v0 * 0.70710678118654752f));
            float g1v = 0.5f * v1 * (1.f + erff(v1 * 0.70710678118654752f));
            float g2v = 0.5f * v2 * (1.f + erff(v2 * 0.70710678118654752f));
            float g3 = 0.5f * v3 * (1.f + erff(v3 * 0.70710678118654752f));
            if (r0 < R_TOTAL)
                *(float2*)(g_mid + (size_t)r0 * F_DIM + col) = make_float2(g0, g1v);
            if (r1 < R_TOTAL)
                *(float2*)(g_mid + (size_t)r1 * F_DIM + col) = make_float2(g2v, g3);
        }
    }
}

// ---------------------------------------------------------------------------
// Kernel 5: out = LN2(g_h + g_mid @ W2 + b2). grid 488, block 256. K=256.
// ---------------------------------------------------------------------------
__global__ void __launch_bounds__(256) k_ffn2_ln2(const float* __restrict__ W2,
                                                  const float* __restrict__ b2,
                                                  const float* __restrict__ g2,
                                                  const float* __restrict__ bt2,
                                                  float* __restrict__ out) {
    extern __shared__ char sm[];
    float* smf = (float*)sm;
    const int row0 = blockIdx.x << 7;

    float acc[4][4][4];
    gemm_bf16(sm, g_mid, F_DIM, row0, W2, D_DIM, 0, F_DIM, acc);
    stage_c(smf, acc);

    const int tid = threadIdx.x;
    if (tid < 128) {
        int row = row0 + tid;
        if (row < R_TOTAL) {
            const float* Cr = smf + tid * CS_STRIDE;
            const float* hr = g_h + (size_t)row * D_DIM;
            float s1 = 0.f, s2 = 0.f;
            #pragma unroll
            for (int c = 0; c < 128; c++) {
                float v = Cr[c] + b2[c] + hr[c];
                s1 += v; s2 += v * v;
            }
            float mean = s1 * (1.f / 128.f);
            float var  = s2 * (1.f / 128.f) - mean * mean;
            float rstd = rsqrtf(var + 1e-5f);
            float* orow = out + (size_t)row * D_DIM;
            #pragma unroll
            for (int c = 0; c < 128; c += 4) {
                float4 o;
                o.x = (Cr[c]     + b2[c]     + hr[c]     - mean) * rstd * g2[c]     + bt2[c];
                o.y = (Cr[c + 1] + b2[c + 1] + hr[c + 1] - mean) * rstd * g2[c + 1] + bt2[c + 1];
                o.z = (Cr[c + 2] + b2[c + 2] + hr[c + 2] - mean) * rstd * g2[c + 2] + bt2[c + 2];
                o.w = (Cr[c + 3] + b2[c + 3] + hr[c + 3] - mean) * rstd * g2[c + 3] + bt2[c + 3];
                *(float4*)(orow + c) = o;
            }
        }
    }
}

// ---------------------------------------------------------------------------
extern "C" void kernel_launch(void* const* d_in, const int* in_sizes, int n_in,
                              void* d_out, int out_size) {
    const float* x     = (const float*)d_in[0];
    const float* Wq    = (const float*)d_in[1];
    const float* bq    = (const float*)d_in[2];
    const float* Wk    = (const float*)d_in[3];
    const float* bk    = (const float*)d_in[4];
    const float* Wv    = (const float*)d_in[5];
    const float* bv    = (const float*)d_in[6];
    const float* Wo    = (const float*)d_in[7];
    const float* bo    = (const float*)d_in[8];
    const float* ln1_g = (const float*)d_in[9];
    const float* ln1_b = (const float*)d_in[10];
    const float* W1    = (const float*)d_in[11];
    const float* b1    = (const float*)d_in[12];
    const float* W2    = (const float*)d_in[13];
    const float* b2    = (const float*)d_in[14];
    const float* ln2_g = (const float*)d_in[15];
    const float* ln2_b = (const float*)d_in[16];
    float* out = (float*)d_out;

    cudaFuncSetAttribute(k_projo_ln1, cudaFuncAttributeMaxDynamicSharedMemorySize, LN_SMEM);
    cudaFuncSetAttribute(k_ffn2_ln2,  cudaFuncAttributeMaxDynamicSharedMemorySize, LN_SMEM);

    k_qkv<<<dim3(M_TILES, 3), 256, TILE_SMEM>>>(x, Wq, bq, Wk, bk, Wv, bv);
    attn_kernel<<<NB * H_HEADS * TT, 256>>>();
    k_projo_ln1<<<M_TILES, 256, LN_SMEM>>>(x, Wo, bo, ln1_g, ln1_b);
    k_ffn1<<<dim3(M_TILES, 2), 256, TILE_SMEM>>>(W1, b1);
    k_ffn2_ln2<<<M_TILES, 256, LN_SMEM>>>(W2, b2, ln2_g, ln2_b, out);
}

// round 7
// speedup vs baseline: 3.4239x; 1.0790x over previous
#include <cuda_runtime.h>
#include <cuda_bf16.h>
#include <math.h>
#include <stdint.h>

// Problem constants
#define NB 16
#define TT 12
#define NN 325
#define D_DIM 128
#define F_DIM 256
#define H_HEADS 8
#define HD 16
#define R_TOTAL (NB*TT*NN)   // 62400
#define M_TILES ((R_TOTAL + 127) / 128)   // 488

// Attention padding
#define NKP 336
#define NPAD (NKP - NN)
#define VT_STRIDE 344

// ---------------------------------------------------------------------------
// Scratch (device globals: allocation-guard safe)
// ---------------------------------------------------------------------------
__device__ __nv_bfloat16 g_xb [R_TOTAL * D_DIM];
__device__ __nv_bfloat16 g_qb [R_TOTAL * D_DIM];
__device__ __nv_bfloat16 g_kb [R_TOTAL * D_DIM];
__device__ __nv_bfloat16 g_vb [R_TOTAL * D_DIM];
__device__ __nv_bfloat16 g_attb[R_TOTAL * D_DIM];
__device__ __nv_bfloat16 g_hb [R_TOTAL * D_DIM];
__device__ __nv_bfloat16 g_midb[R_TOTAL * F_DIM];
__device__ float         g_h  [R_TOTAL * D_DIM];   // fp32 residual for LN2
__device__ __nv_bfloat16 g_Wqb[D_DIM * D_DIM];
__device__ __nv_bfloat16 g_Wkb[D_DIM * D_DIM];
__device__ __nv_bfloat16 g_Wvb[D_DIM * D_DIM];
__device__ __nv_bfloat16 g_Wob[D_DIM * D_DIM];
__device__ __nv_bfloat16 g_W1b[D_DIM * F_DIM];
__device__ __nv_bfloat16 g_W2b[F_DIM * D_DIM];

// ---------------------------------------------------------------------------
// Common helpers
// ---------------------------------------------------------------------------
__device__ __forceinline__ uint32_t packbf(float x, float y) {  // lo=x, hi=y
    uint32_t r;
    asm("cvt.rn.bf16x2.f32 %0, %1, %2;" : "=r"(r) : "f"(y), "f"(x));
    return r;
}

__device__ __forceinline__ void mma_bf16(float c[4], const uint32_t a[4], const uint32_t b[2]) {
    asm volatile(
        "mma.sync.aligned.m16n8k16.row.col.f32.bf16.bf16.f32 "
        "{%0,%1,%2,%3}, {%4,%5,%6,%7}, {%8,%9}, {%0,%1,%2,%3};"
        : "+f"(c[0]), "+f"(c[1]), "+f"(c[2]), "+f"(c[3])
        : "r"(a[0]), "r"(a[1]), "r"(a[2]), "r"(a[3]), "r"(b[0]), "r"(b[1]));
}

__device__ __forceinline__ void ldsm_x4(uint32_t r[4], uint32_t addr) {
    asm volatile("ldmatrix.sync.aligned.m8n8.x4.shared.b16 {%0,%1,%2,%3}, [%4];"
        : "=r"(r[0]), "=r"(r[1]), "=r"(r[2]), "=r"(r[3]) : "r"(addr));
}
__device__ __forceinline__ void ldsm_x2t(uint32_t r[2], uint32_t addr) {
    asm volatile("ldmatrix.sync.aligned.m8n8.x2.trans.shared.b16 {%0,%1}, [%2];"
        : "=r"(r[0]), "=r"(r[1]) : "r"(addr));
}

__device__ __forceinline__ void cp16(uint32_t smaddr, const void* gaddr) {
    asm volatile("cp.async.cg.shared.global [%0], [%1], 16;" :: "r"(smaddr), "l"(gaddr));
}
__device__ __forceinline__ void cp_commit() {
    asm volatile("cp.async.commit_group;");
}
template <int N>
__device__ __forceinline__ void cp_wait() {
    asm volatile("cp.async.wait_group %0;" :: "n"(N));
}

// ---------------------------------------------------------------------------
// Pipelined bf16 GEMM: CTA 128x128, 8 warps (2x4), warp 64x32, 2-stage cp.async.
// Stage: As[128][20 u32] + Bs[32][68 u32].
// ---------------------------------------------------------------------------
#define AS_U32 20
#define BS_U32 68
#define A_STAGE (128 * AS_U32 * 4)          // 10240
#define B_STAGE (32 * BS_U32 * 4)           // 8704
#define STAGE_BYTES (A_STAGE + B_STAGE)     // 18944
#define TILE_SMEM (2 * STAGE_BYTES)         // 37888
#define CS_STRIDE 130
#define LN_SMEM (128 * CS_STRIDE * 4)       // 66560

__device__ __forceinline__ void fill_stage(uint32_t smBase, int s,
                                           const __nv_bfloat16* __restrict__ A, int lda, int row0,
                                           const __nv_bfloat16* __restrict__ B, int ldb, int bcol0,
                                           int kofs) {
    const int tid = threadIdx.x;
    const uint32_t aDst = smBase + s * STAGE_BYTES;
    const uint32_t bDst = aDst + A_STAGE;
    #pragma unroll
    for (int it = 0; it < 2; it++) {
        int idx = tid + it * 256;
        int r = idx >> 2, seg = idx & 3;
        int row = row0 + r;
        if (row > R_TOTAL - 1) row = R_TOTAL - 1;
        cp16(aDst + r * (AS_U32 * 4) + seg * 16,
             A + (size_t)row * lda + kofs + seg * 8);
    }
    #pragma unroll
    for (int it = 0; it < 2; it++) {
        int idx = tid + it * 256;
        int k = idx >> 4, seg = idx & 15;
        cp16(bDst + k * (BS_U32 * 4) + seg * 16,
             B + (size_t)(kofs + k) * ldb + bcol0 + seg * 8);
    }
    cp_commit();
}

__device__ __forceinline__ void gemm_pipe(char* sm,
                                          const __nv_bfloat16* __restrict__ A, int lda, int row0,
                                          const __nv_bfloat16* __restrict__ B, int ldb, int bcol0,
                                          int K, float acc[4][4][4]) {
    const int tid  = threadIdx.x;
    const int warp = tid >> 5;
    const int lane = tid & 31;
    const int wm   = warp >> 2;
    const int wn   = warp & 3;
    const uint32_t smBase = (uint32_t)__cvta_generic_to_shared(sm);

    #pragma unroll
    for (int i = 0; i < 4; i++)
        #pragma unroll
        for (int j = 0; j < 4; j++)
            #pragma unroll
            for (int r = 0; r < 4; r++) acc[i][j][r] = 0.f;

    const int nchunk = K >> 5;
    fill_stage(smBase, 0, A, lda, row0, B, ldb, bcol0, 0);

    for (int ch = 0; ch < nchunk; ch++) {
        if (ch + 1 < nchunk) {
            fill_stage(smBase, (ch + 1) & 1, A, lda, row0, B, ldb, bcol0, (ch + 1) << 5);
            cp_wait<1>();
        } else {
            cp_wait<0>();
        }
        __syncthreads();

        const int s = ch & 1;
        const uint32_t sa = smBase + s * STAGE_BYTES;
        const uint32_t sb = sa + A_STAGE;
        const uint32_t aBase = sa + (uint32_t)(wm * 64 + (lane & 15)) * (AS_U32 * 4)
                             + ((uint32_t)(lane >> 4) << 4);
        const uint32_t bBase = sb + (uint32_t)(lane & 15) * (BS_U32 * 4) + (uint32_t)wn * 64;

        #pragma unroll
        for (int ks = 0; ks < 2; ks++) {
            uint32_t af[4][4], bfr[4][2];
            #pragma unroll
            for (int mt = 0; mt < 4; mt++)
                ldsm_x4(af[mt], aBase + mt * (16 * AS_U32 * 4) + ks * 32);
            #pragma unroll
            for (int nt = 0; nt < 4; nt++)
                ldsm_x2t(bfr[nt], bBase + ks * (16 * BS_U32 * 4) + nt * 16);
            #pragma unroll
            for (int mt = 0; mt < 4; mt++)
                #pragma unroll
                for (int nt = 0; nt < 4; nt++)
                    mma_bf16(acc[mt][nt], af[mt], bfr[nt]);
        }
        __syncthreads();
    }
}

// Stage accumulators to smem C[128][130] for row-wise epilogues.
__device__ __forceinline__ void stage_c(float* smf, float acc[4][4][4]) {
    const int tid  = threadIdx.x;
    const int warp = tid >> 5;
    const int lane = tid & 31;
    const int gid  = lane >> 2;
    const int tig  = lane & 3;
    const int wm   = warp >> 2;
    const int wn   = warp & 3;
    #pragma unroll
    for (int mt = 0; mt < 4; mt++) {
        #pragma unroll
        for (int nt = 0; nt < 4; nt++) {
            int row = wm * 64 + mt * 16 + gid;
            int col = wn * 32 + nt * 8 + (tig << 1);
            *(float2*)(smf + row * CS_STRIDE + col)       = make_float2(acc[mt][nt][0], acc[mt][nt][1]);
            *(float2*)(smf + (row + 8) * CS_STRIDE + col) = make_float2(acc[mt][nt][2], acc[mt][nt][3]);
        }
    }
    __syncthreads();
}

// ---------------------------------------------------------------------------
// Conversion kernels (fp32 -> bf16)
// ---------------------------------------------------------------------------
__global__ void k_cvt_x(const float* __restrict__ x) {
    uint32_t* dst = (uint32_t*)g_xb;
    const int n4 = R_TOTAL * D_DIM / 4;
    for (int i = blockIdx.x * blockDim.x + threadIdx.x; i < n4; i += gridDim.x * blockDim.x) {
        float4 v = *(const float4*)(x + (size_t)i * 4);
        dst[i * 2]     = packbf(v.x, v.y);
        dst[i * 2 + 1] = packbf(v.z, v.w);
    }
}

__global__ void k_cvt_w(const float* __restrict__ Wq, const float* __restrict__ Wk,
                        const float* __restrict__ Wv, const float* __restrict__ Wo,
                        const float* __restrict__ W1, const float* __restrict__ W2) {
    const int n4 = (4 * 16384 + 2 * 32768) / 4;   // 32768
    for (int i = blockIdx.x * blockDim.x + threadIdx.x; i < n4; i += gridDim.x * blockDim.x) {
        const float* src;
        __nv_bfloat16* dst;
        int off;
        if      (i < 4096)  { src = Wq; dst = g_Wqb; off = i; }
        else if (i < 8192)  { src = Wk; dst = g_Wkb; off = i - 4096; }
        else if (i < 12288) { src = Wv; dst = g_Wvb; off = i - 8192; }
        else if (i < 16384) { src = Wo; dst = g_Wob; off = i - 12288; }
        else if (i < 24576) { src = W1; dst = g_W1b; off = i - 16384; }
        else                { src = W2; dst = g_W2b; off = i - 24576; }
        float4 v = *(const float4*)(src + (size_t)off * 4);
        uint32_t* d = (uint32_t*)dst + off * 2;
        d[0] = packbf(v.x, v.y);
        d[1] = packbf(v.z, v.w);
    }
}

// ---------------------------------------------------------------------------
// Kernel 1: QKV projections, bf16 out. grid (488, 3), block 256.
// ---------------------------------------------------------------------------
__global__ void __launch_bounds__(256) k_qkv(const float* __restrict__ bq,
                                             const float* __restrict__ bk,
                                             const float* __restrict__ bv) {
    extern __shared__ char sm[];
    const int which = blockIdx.y;
    const __nv_bfloat16* W = (which == 0) ? g_Wqb : (which == 1) ? g_Wkb : g_Wvb;
    const float* bias      = (which == 0) ? bq : (which == 1) ? bk : bv;
    __nv_bfloat16* out     = (which == 0) ? g_qb : (which == 1) ? g_kb : g_vb;
    const int row0 = blockIdx.x << 7;

    float acc[4][4][4];
    gemm_pipe(sm, g_xb, D_DIM, row0, W, D_DIM, 0, D_DIM, acc);

    const int tid  = threadIdx.x;
    const int warp = tid >> 5;
    const int lane = tid & 31;
    const int gid  = lane >> 2;
    const int tig  = lane & 3;
    const int wm   = warp >> 2;
    const int wn   = warp & 3;

    #pragma unroll
    for (int mt = 0; mt < 4; mt++) {
        int r0 = row0 + wm * 64 + mt * 16 + gid;
        int r1 = r0 + 8;
        #pragma unroll
        for (int nt = 0; nt < 4; nt++) {
            int col = wn * 32 + nt * 8 + (tig << 1);
            float b0 = bias[col], b1 = bias[col + 1];
            if (r0 < R_TOTAL)
                *(uint32_t*)(out + (size_t)r0 * D_DIM + col) = packbf(acc[mt][nt][0] + b0, acc[mt][nt][1] + b1);
            if (r1 < R_TOTAL)
                *(uint32_t*)(out + (size_t)r1 * D_DIM + col) = packbf(acc[mt][nt][2] + b0, acc[mt][nt][3] + b1);
        }
    }
}

// ---------------------------------------------------------------------------
// Kernel 2: tensorized attention per (b,h,t). grid = 1536, block = 256.
// ---------------------------------------------------------------------------
__global__ void __launch_bounds__(256) attn_kernel() {
    __shared__ __align__(16) uint32_t Qs[NKP * 8];
    __shared__ __align__(16) uint32_t Ks[NKP * 8];
    __shared__ __align__(16) uint32_t Vt[HD * (VT_STRIDE / 2)];

    const int bid = blockIdx.x;
    const int t = bid % TT;
    const int h = (bid / TT) % H_HEADS;
    const int b = bid / (TT * H_HEADS);
    const int row0 = (b * TT + t) * NN;
    const int hoff = h * HD;
    const int tid = threadIdx.x;

    __nv_bfloat16* Vtb = (__nv_bfloat16*)Vt;

    for (int idx = tid; idx < NKP * 2; idx += 256) {
        int m = idx >> 1;
        int seg = idx & 1;
        uint4 qv, kv, vv;
        if (m < NN) {
            size_t base = (size_t)(row0 + m) * D_DIM + hoff + seg * 8;
            qv = *(const uint4*)(g_qb + base);
            kv = *(const uint4*)(g_kb + base);
            vv = *(const uint4*)(g_vb + base);
        } else {
            qv = kv = vv = make_uint4(0, 0, 0, 0);
        }
        *(uint4*)(Qs + m * 8 + seg * 4) = qv;
        *(uint4*)(Ks + m * 8 + seg * 4) = kv;
        int d0 = seg * 8;
        uint32_t vu[4] = {vv.x, vv.y, vv.z, vv.w};
        #pragma unroll
        for (int j = 0; j < 4; j++) {
            __nv_bfloat162 p = *(__nv_bfloat162*)&vu[j];
            Vtb[(d0 + 2 * j)     * VT_STRIDE + m] = p.x;
            Vtb[(d0 + 2 * j + 1) * VT_STRIDE + m] = p.y;
        }
    }
    __syncthreads();

    const int warp = tid >> 5;
    const int lane = tid & 31;
    const int gid  = lane >> 2;
    const int tig  = lane & 3;

    for (int mt = warp; mt < 21; mt += 8) {
        const int m0 = mt << 4;
        uint32_t qa[4];
        qa[0] = Qs[(m0 + gid) * 8 + tig];
        qa[1] = Qs[(m0 + gid + 8) * 8 + tig];
        qa[2] = Qs[(m0 + gid) * 8 + tig + 4];
        qa[3] = Qs[(m0 + gid + 8) * 8 + tig + 4];

        float oc0[4] = {0.f, 0.f, 0.f, 0.f};
        float oc1[4] = {0.f, 0.f, 0.f, 0.f};
        float rs0 = 0.f, rs1 = 0.f;

        for (int j = 0; j < 21; j++) {
            float c0[4] = {0.f, 0.f, 0.f, 0.f};
            float c1[4] = {0.f, 0.f, 0.f, 0.f};
            {
                int nr = (j << 4) + gid;
                uint32_t kb[2];
                kb[0] = Ks[nr * 8 + tig];
                kb[1] = Ks[nr * 8 + tig + 4];
                mma_bf16(c0, qa, kb);
                kb[0] = Ks[(nr + 8) * 8 + tig];
                kb[1] = Ks[(nr + 8) * 8 + tig + 4];
                mma_bf16(c1, qa, kb);
            }
            float p00 = __expf(c0[0] * 0.25f);
            float p01 = __expf(c0[1] * 0.25f);
            float p02 = __expf(c0[2] * 0.25f);
            float p03 = __expf(c0[3] * 0.25f);
            float p10 = __expf(c1[0] * 0.25f);
            float p11 = __expf(c1[1] * 0.25f);
            float p12 = __expf(c1[2] * 0.25f);
            float p13 = __expf(c1[3] * 0.25f);
            rs0 += (p00 + p01) + (p10 + p11);
            rs1 += (p02 + p03) + (p12 + p13);

            uint32_t pa[4];
            pa[0] = packbf(p00, p01);
            pa[1] = packbf(p02, p03);
            pa[2] = packbf(p10, p11);
            pa[3] = packbf(p12, p13);

            const int kb0 = (j << 3);
            uint32_t vb[2];
            vb[0] = Vt[(gid)     * (VT_STRIDE / 2) + kb0 + tig];
            vb[1] = Vt[(gid)     * (VT_STRIDE / 2) + kb0 + tig + 4];
            mma_bf16(oc0, pa, vb);
            vb[0] = Vt[(gid + 8) * (VT_STRIDE / 2) + kb0 + tig];
            vb[1] = Vt[(gid + 8) * (VT_STRIDE / 2) + kb0 + tig + 4];
            mma_bf16(oc1, pa, vb);
        }

        rs0 += __shfl_xor_sync(0xffffffffu, rs0, 1);
        rs0 += __shfl_xor_sync(0xffffffffu, rs0, 2);
        rs1 += __shfl_xor_sync(0xffffffffu, rs1, 1);
        rs1 += __shfl_xor_sync(0xffffffffu, rs1, 2);
        float i0 = 1.f / (rs0 - (float)NPAD);
        float i1 = 1.f / (rs1 - (float)NPAD);

        int r0 = m0 + gid;
        int r1 = m0 + gid + 8;
        if (r0 < NN) {
            __nv_bfloat16* op = g_attb + (size_t)(row0 + r0) * D_DIM + hoff;
            *(uint32_t*)(op + 2 * tig)     = packbf(oc0[0] * i0, oc0[1] * i0);
            *(uint32_t*)(op + 8 + 2 * tig) = packbf(oc1[0] * i0, oc1[1] * i0);
        }
        if (r1 < NN) {
            __nv_bfloat16* op = g_attb + (size_t)(row0 + r1) * D_DIM + hoff;
            *(uint32_t*)(op + 2 * tig)     = packbf(oc0[2] * i1, oc0[3] * i1);
            *(uint32_t*)(op + 8 + 2 * tig) = packbf(oc1[2] * i1, oc1[3] * i1);
        }
    }
}

// ---------------------------------------------------------------------------
// Kernel 3: h = LN1(x + att @ Wo + bo); writes g_h (fp32) + g_hb (bf16).
// ---------------------------------------------------------------------------
__global__ void __launch_bounds__(256) k_projo_ln1(const float* __restrict__ x,
                                                   const float* __restrict__ bo,
                                                   const float* __restrict__ g1, const float* __restrict__ b1) {
    extern __shared__ char sm[];
    float* smf = (float*)sm;
    const int row0 = blockIdx.x << 7;

    float acc[4][4][4];
    gemm_pipe(sm, g_attb, D_DIM, row0, g_Wob, D_DIM, 0, D_DIM, acc);
    stage_c(smf, acc);

    const int tid = threadIdx.x;
    if (tid < 128) {
        int row = row0 + tid;
        if (row < R_TOTAL) {
            const float* Cr = smf + tid * CS_STRIDE;
            const float* xr = x + (size_t)row * D_DIM;
            float s1 = 0.f, s2 = 0.f;
            #pragma unroll
            for (int c = 0; c < 128; c++) {
                float v = Cr[c] + bo[c] + xr[c];
                s1 += v; s2 += v * v;
            }
            float mean = s1 * (1.f / 128.f);
            float var  = s2 * (1.f / 128.f) - mean * mean;
            float rstd = rsqrtf(var + 1e-5f);
            float* hr = g_h + (size_t)row * D_DIM;
            uint32_t* hb = (uint32_t*)(g_hb + (size_t)row * D_DIM);
            #pragma unroll
            for (int c = 0; c < 128; c += 4) {
                float4 o;
                o.x = (Cr[c]     + bo[c]     + xr[c]     - mean) * rstd * g1[c]     + b1[c];
                o.y = (Cr[c + 1] + bo[c + 1] + xr[c + 1] - mean) * rstd * g1[c + 1] + b1[c + 1];
                o.z = (Cr[c + 2] + bo[c + 2] + xr[c + 2] - mean) * rstd * g1[c + 2] + b1[c + 2];
                o.w = (Cr[c + 3] + bo[c + 3] + xr[c + 3] - mean) * rstd * g1[c + 3] + b1[c + 3];
                *(float4*)(hr + c) = o;
                hb[c >> 1]       = packbf(o.x, o.y);
                hb[(c >> 1) + 1] = packbf(o.z, o.w);
            }
        }
    }
}

// ---------------------------------------------------------------------------
// Kernel 4: mid = gelu(h @ W1 + b1), bf16 out. grid (488, 2), block 256.
// ---------------------------------------------------------------------------
__global__ void __launch_bounds__(256) k_ffn1(const float* __restrict__ b1) {
    extern __shared__ char sm[];
    const int row0 = blockIdx.x << 7;
    const int col0 = blockIdx.y << 7;

    float acc[4][4][4];
    gemm_pipe(sm, g_hb, D_DIM, row0, g_W1b, F_DIM, col0, D_DIM, acc);

    const int tid  = threadIdx.x;
    const int warp = tid >> 5;
    const int lane = tid & 31;
    const int gid  = lane >> 2;
    const int tig  = lane & 3;
    const int wm   = warp >> 2;
    const int wn   = warp & 3;

    #pragma unroll
    for (int mt = 0; mt < 4; mt++) {
        int r0 = row0 + wm * 64 + mt * 16 + gid;
        int r1 = r0 + 8;
        #pragma unroll
        for (int nt = 0; nt < 4; nt++) {
            int col = col0 + wn * 32 + nt * 8 + (tig << 1);
            float b0 = b1[col], bb1 = b1[col + 1];
            float v0 = acc[mt][nt][0] + b0;
            float v1 = acc[mt][nt][1] + bb1;
            float v2 = acc[mt][nt][2] + b0;
            float v3 = acc[mt][nt][3] + bb1;
            float e0 = 0.5f * v0 * (1.f + erff(v0 * 0.70710678118654752f));
            float e1 = 0.5f * v1 * (1.f + erff(v1 * 0.70710678118654752f));
            float e2 = 0.5f * v2 * (1.f + erff(v2 * 0.70710678118654752f));
            float e3 = 0.5f * v3 * (1.f + erff(v3 * 0.70710678118654752f));
            if (r0 < R_TOTAL)
                *(uint32_t*)(g_midb + (size_t)r0 * F_DIM + col) = packbf(e0, e1);
            if (r1 < R_TOTAL)
                *(uint32_t*)(g_midb + (size_t)r1 * F_DIM + col) = packbf(e2, e3);
        }
    }
}

// ---------------------------------------------------------------------------
// Kernel 5: out = LN2(h + mid @ W2 + b2). grid 488, block 256. K=256.
// ---------------------------------------------------------------------------
__global__ void __launch_bounds__(256) k_ffn2_ln2(const float* __restrict__ b2,
                                                  const float* __restrict__ g2,
                                                  const float* __restrict__ bt2,
                                                  float* __restrict__ out) {
    extern __shared__ char sm[];
    float* smf = (float*)sm;
    const int row0 = blockIdx.x << 7;

    float acc[4][4][4];
    gemm_pipe(sm, g_midb, F_DIM, row0, g_W2b, D_DIM, 0, F_DIM, acc);
    stage_c(smf, acc);

    const int tid = threadIdx.x;
    if (tid < 128) {
        int row = row0 + tid;
        if (row < R_TOTAL) {
            const float* Cr = smf + tid * CS_STRIDE;
            const float* hr = g_h + (size_t)row * D_DIM;
            float s1 = 0.f, s2 = 0.f;
            #pragma unroll
            for (int c = 0; c < 128; c++) {
                float v = Cr[c] + b2[c] + hr[c];
                s1 += v; s2 += v * v;
            }
            float mean = s1 * (1.f / 128.f);
            float var  = s2 * (1.f / 128.f) - mean * mean;
            float rstd = rsqrtf(var + 1e-5f);
            float* orow = out + (size_t)row * D_DIM;
            #pragma unroll
            for (int c = 0; c < 128; c += 4) {
                float4 o;
                o.x = (Cr[c]     + b2[c]     + hr[c]     - mean) * rstd * g2[c]     + bt2[c];
                o.y = (Cr[c + 1] + b2[c + 1] + hr[c + 1] - mean) * rstd * g2[c + 1] + bt2[c + 1];
                o.z = (Cr[c + 2] + b2[c + 2] + hr[c + 2] - mean) * rstd * g2[c + 2] + bt2[c + 2];
                o.w = (Cr[c + 3] + b2[c + 3] + hr[c + 3] - mean) * rstd * g2[c + 3] + bt2[c + 3];
                *(float4*)(orow + c) = o;
            }
        }
    }
}

// ---------------------------------------------------------------------------
extern "C" void kernel_launch(void* const* d_in, const int* in_sizes, int n_in,
                              void* d_out, int out_size) {
    const float* x     = (const float*)d_in[0];
    const float* Wq    = (const float*)d_in[1];
    const float* bq    = (const float*)d_in[2];
    const float* Wk    = (const float*)d_in[3];
    const float* bk    = (const float*)d_in[4];
    const float* Wv    = (const float*)d_in[5];
    const float* bv    = (const float*)d_in[6];
    const float* Wo    = (const float*)d_in[7];
    const float* bo    = (const float*)d_in[8];
    const float* ln1_g = (const float*)d_in[9];
    const float* ln1_b = (const float*)d_in[10];
    const float* W1    = (const float*)d_in[11];
    const float* b1    = (const float*)d_in[12];
    const float* W2    = (const float*)d_in[13];
    const float* b2    = (const float*)d_in[14];
    const float* ln2_g = (const float*)d_in[15];
    const float* ln2_b = (const float*)d_in[16];
    float* out = (float*)d_out;

    cudaFuncSetAttribute(k_projo_ln1, cudaFuncAttributeMaxDynamicSharedMemorySize, LN_SMEM);
    cudaFuncSetAttribute(k_ffn2_ln2,  cudaFuncAttributeMaxDynamicSharedMemorySize, LN_SMEM);

    k_cvt_w<<<64, 512>>>(Wq, Wk, Wv, Wo, W1, W2);
    k_cvt_x<<<1024, 512>>>(x);
    k_qkv<<<dim3(M_TILES, 3), 256, TILE_SMEM>>>(bq, bk, bv);
    attn_kernel<<<NB * H_HEADS * TT, 256>>>();
    k_projo_ln1<<<M_TILES, 256, LN_SMEM>>>(x, bo, ln1_g, ln1_b);
    k_ffn1<<<dim3(M_TILES, 2), 256, TILE_SMEM>>>(b1);
    k_ffn2_ln2<<<M_TILES, 256, LN_SMEM>>>(b2, ln2_g, ln2_b, out);
}

// round 8
// speedup vs baseline: 3.5640x; 1.0409x over previous
#include <cuda_runtime.h>
#include <cuda_bf16.h>
#include <math.h>
#include <stdint.h>

// Problem constants
#define NB 16
#define TT 12
#define NN 325
#define D_DIM 128
#define F_DIM 256
#define H_HEADS 8
#define HD 16
#define R_TOTAL (NB*TT*NN)   // 62400
#define M_TILES ((R_TOTAL + 127) / 128)   // 488

// Attention padding
#define NKP 336
#define VT_STRIDE 344        // bf16 per Vt row (172 u32); 688B row stride

// log2(e)/4: folded into q so attention uses plain exp2
#define QSCALE 0.36067376022224085f

// ---------------------------------------------------------------------------
// Scratch (device globals: allocation-guard safe)
// ---------------------------------------------------------------------------
__device__ __nv_bfloat16 g_xb [R_TOTAL * D_DIM];
__device__ __nv_bfloat16 g_qb [R_TOTAL * D_DIM];   // pre-scaled by QSCALE
__device__ __nv_bfloat16 g_kb [R_TOTAL * D_DIM];
__device__ __nv_bfloat16 g_vb [R_TOTAL * D_DIM];
__device__ __nv_bfloat16 g_attb[R_TOTAL * D_DIM];
__device__ __nv_bfloat16 g_hb [R_TOTAL * D_DIM];
__device__ __nv_bfloat16 g_midb[R_TOTAL * F_DIM];
__device__ float         g_h  [R_TOTAL * D_DIM];   // fp32 residual for LN2
__device__ __nv_bfloat16 g_Wqb[D_DIM * D_DIM];
__device__ __nv_bfloat16 g_Wkb[D_DIM * D_DIM];
__device__ __nv_bfloat16 g_Wvb[D_DIM * D_DIM];
__device__ __nv_bfloat16 g_Wob[D_DIM * D_DIM];
__device__ __nv_bfloat16 g_W1b[D_DIM * F_DIM];
__device__ __nv_bfloat16 g_W2b[F_DIM * D_DIM];

// ---------------------------------------------------------------------------
// Common helpers
// ---------------------------------------------------------------------------
__device__ __forceinline__ uint32_t packbf(float x, float y) {  // lo=x, hi=y
    uint32_t r;
    asm("cvt.rn.bf16x2.f32 %0, %1, %2;" : "=r"(r) : "f"(y), "f"(x));
    return r;
}

__device__ __forceinline__ float ex2(float x) {
    float r;
    asm("ex2.approx.f32 %0, %1;" : "=f"(r) : "f"(x));
    return r;
}

__device__ __forceinline__ void mma_bf16(float c[4], const uint32_t a[4], const uint32_t b[2]) {
    asm volatile(
        "mma.sync.aligned.m16n8k16.row.col.f32.bf16.bf16.f32 "
        "{%0,%1,%2,%3}, {%4,%5,%6,%7}, {%8,%9}, {%0,%1,%2,%3};"
        : "+f"(c[0]), "+f"(c[1]), "+f"(c[2]), "+f"(c[3])
        : "r"(a[0]), "r"(a[1]), "r"(a[2]), "r"(a[3]), "r"(b[0]), "r"(b[1]));
}

__device__ __forceinline__ void ldsm_x4(uint32_t r[4], uint32_t addr) {
    asm volatile("ldmatrix.sync.aligned.m8n8.x4.shared.b16 {%0,%1,%2,%3}, [%4];"
        : "=r"(r[0]), "=r"(r[1]), "=r"(r[2]), "=r"(r[3]) : "r"(addr));
}
__device__ __forceinline__ void ldsm_x2(uint32_t r[2], uint32_t addr) {
    asm volatile("ldmatrix.sync.aligned.m8n8.x2.shared.b16 {%0,%1}, [%2];"
        : "=r"(r[0]), "=r"(r[1]) : "r"(addr));
}
__device__ __forceinline__ void ldsm_x2t(uint32_t r[2], uint32_t addr) {
    asm volatile("ldmatrix.sync.aligned.m8n8.x2.trans.shared.b16 {%0,%1}, [%2];"
        : "=r"(r[0]), "=r"(r[1]) : "r"(addr));
}

__device__ __forceinline__ void cp16(uint32_t smaddr, const void* gaddr) {
    asm volatile("cp.async.cg.shared.global [%0], [%1], 16;" :: "r"(smaddr), "l"(gaddr));
}
__device__ __forceinline__ void cp_commit() {
    asm volatile("cp.async.commit_group;");
}
template <int N>
__device__ __forceinline__ void cp_wait() {
    asm volatile("cp.async.wait_group %0;" :: "n"(N));
}

// ---------------------------------------------------------------------------
// GEMM geometry: CTA 128x128, 8 warps (2x4), warp 64x32.
// Streaming stage (A+B) for projo/ffn2; resident-A + B-stream for qkv/ffn1.
// ---------------------------------------------------------------------------
#define AS_U32 20
#define BS_U32 68
#define A_STAGE (128 * AS_U32 * 4)          // 10240
#define B_STAGE (32 * BS_U32 * 4)           // 8704
#define STAGE_BYTES (A_STAGE + B_STAGE)     // 18944
#define TILE_SMEM (2 * STAGE_BYTES)         // 37888
#define CS_STRIDE 130
#define LN_SMEM (128 * CS_STRIDE * 4)       // 66560

// resident-A layout: 128 rows x 128 bf16, row stride 272B (16B pad)
#define ATILE_STRIDE 272
#define ATILE_BYTES (128 * ATILE_STRIDE)    // 34816
#define MP_SMEM (ATILE_BYTES + 2 * B_STAGE) // 52224

// ---- streaming pipeline (unchanged, used by projo/ffn2) ----
__device__ __forceinline__ void fill_stage(uint32_t smBase, int s,
                                           const __nv_bfloat16* __restrict__ A, int lda, int row0,
                                           const __nv_bfloat16* __restrict__ B, int ldb, int bcol0,
                                           int kofs) {
    const int tid = threadIdx.x;
    const uint32_t aDst = smBase + s * STAGE_BYTES;
    const uint32_t bDst = aDst + A_STAGE;
    #pragma unroll
    for (int it = 0; it < 2; it++) {
        int idx = tid + it * 256;
        int r = idx >> 2, seg = idx & 3;
        int row = row0 + r;
        if (row > R_TOTAL - 1) row = R_TOTAL - 1;
        cp16(aDst + r * (AS_U32 * 4) + seg * 16,
             A + (size_t)row * lda + kofs + seg * 8);
    }
    #pragma unroll
    for (int it = 0; it < 2; it++) {
        int idx = tid + it * 256;
        int k = idx >> 4, seg = idx & 15;
        cp16(bDst + k * (BS_U32 * 4) + seg * 16,
             B + (size_t)(kofs + k) * ldb + bcol0 + seg * 8);
    }
    cp_commit();
}

__device__ __forceinline__ void gemm_pipe(char* sm,
                                          const __nv_bfloat16* __restrict__ A, int lda, int row0,
                                          const __nv_bfloat16* __restrict__ B, int ldb, int bcol0,
                                          int K, float acc[4][4][4]) {
    const int tid  = threadIdx.x;
    const int warp = tid >> 5;
    const int lane = tid & 31;
    const int wm   = warp >> 2;
    const int wn   = warp & 3;
    const uint32_t smBase = (uint32_t)__cvta_generic_to_shared(sm);

    #pragma unroll
    for (int i = 0; i < 4; i++)
        #pragma unroll
        for (int j = 0; j < 4; j++)
            #pragma unroll
            for (int r = 0; r < 4; r++) acc[i][j][r] = 0.f;

    const int nchunk = K >> 5;
    fill_stage(smBase, 0, A, lda, row0, B, ldb, bcol0, 0);

    for (int ch = 0; ch < nchunk; ch++) {
        if (ch + 1 < nchunk) {
            fill_stage(smBase, (ch + 1) & 1, A, lda, row0, B, ldb, bcol0, (ch + 1) << 5);
            cp_wait<1>();
        } else {
            cp_wait<0>();
        }
        __syncthreads();

        const int s = ch & 1;
        const uint32_t sa = smBase + s * STAGE_BYTES;
        const uint32_t sb = sa + A_STAGE;
        const uint32_t aBase = sa + (uint32_t)(wm * 64 + (lane & 15)) * (AS_U32 * 4)
                             + ((uint32_t)(lane >> 4) << 4);
        const uint32_t bBase = sb + (uint32_t)(lane & 15) * (BS_U32 * 4) + (uint32_t)wn * 64;

        #pragma unroll
        for (int ks = 0; ks < 2; ks++) {
            uint32_t af[4][4], bfr[4][2];
            #pragma unroll
            for (int mt = 0; mt < 4; mt++)
                ldsm_x4(af[mt], aBase + mt * (16 * AS_U32 * 4) + ks * 32);
            #pragma unroll
            for (int nt = 0; nt < 4; nt++)
                ldsm_x2t(bfr[nt], bBase + ks * (16 * BS_U32 * 4) + nt * 16);
            #pragma unroll
            for (int mt = 0; mt < 4; mt++)
                #pragma unroll
                for (int nt = 0; nt < 4; nt++)
                    mma_bf16(acc[mt][nt], af[mt], bfr[nt]);
        }
        __syncthreads();
    }
}

// ---- resident-A helpers (qkv / ffn1) ----
__device__ __forceinline__ void fill_A_tile(uint32_t aTile,
                                            const __nv_bfloat16* __restrict__ A, int row0) {
    const int tid = threadIdx.x;
    #pragma unroll
    for (int it = 0; it < 8; it++) {
        int idx = tid + it * 256;
        int r = idx >> 4, seg = idx & 15;
        int row = row0 + r;
        if (row > R_TOTAL - 1) row = R_TOTAL - 1;
        cp16(aTile + r * ATILE_STRIDE + seg * 16,
             A + (size_t)row * D_DIM + seg * 8);
    }
}

__device__ __forceinline__ void fill_Bchunk(uint32_t dst,
                                            const __nv_bfloat16* __restrict__ B, int ldb,
                                            int bcol0, int kofs) {
    const int tid = threadIdx.x;
    #pragma unroll
    for (int it = 0; it < 2; it++) {
        int idx = tid + it * 256;
        int k = idx >> 4, seg = idx & 15;
        cp16(dst + k * (BS_U32 * 4) + seg * 16,
             B + (size_t)(kofs + k) * ldb + bcol0 + seg * 8);
    }
    cp_commit();
}

__device__ __forceinline__ void mma_chunk_resA(uint32_t aTile, uint32_t bStage, int ch,
                                               float acc[4][4][4], int wm, int wn, int lane) {
    const uint32_t aBase = aTile + (uint32_t)(wm * 64 + (lane & 15)) * ATILE_STRIDE
                         + (uint32_t)(ch * 64) + ((uint32_t)(lane >> 4) << 4);
    const uint32_t bBase = bStage + (uint32_t)(lane & 15) * (BS_U32 * 4) + (uint32_t)wn * 64;
    #pragma unroll
    for (int ks = 0; ks < 2; ks++) {
        uint32_t af[4][4], bfr[4][2];
        #pragma unroll
        for (int mt = 0; mt < 4; mt++)
            ldsm_x4(af[mt], aBase + mt * (16 * ATILE_STRIDE) + ks * 32);
        #pragma unroll
        for (int nt = 0; nt < 4; nt++)
            ldsm_x2t(bfr[nt], bBase + ks * (16 * BS_U32 * 4) + nt * 16);
        #pragma unroll
        for (int mt = 0; mt < 4; mt++)
            #pragma unroll
            for (int nt = 0; nt < 4; nt++)
                mma_bf16(acc[mt][nt], af[mt], bfr[nt]);
    }
}

// Stage accumulators to smem C[128][130] for row-wise epilogues.
__device__ __forceinline__ void stage_c(float* smf, float acc[4][4][4]) {
    const int tid  = threadIdx.x;
    const int warp = tid >> 5;
    const int lane = tid & 31;
    const int gid  = lane >> 2;
    const int tig  = lane & 3;
    const int wm   = warp >> 2;
    const int wn   = warp & 3;
    #pragma unroll
    for (int mt = 0; mt < 4; mt++) {
        #pragma unroll
        for (int nt = 0; nt < 4; nt++) {
            int row = wm * 64 + mt * 16 + gid;
            int col = wn * 32 + nt * 8 + (tig << 1);
            *(float2*)(smf + row * CS_STRIDE + col)       = make_float2(acc[mt][nt][0], acc[mt][nt][1]);
            *(float2*)(smf + (row + 8) * CS_STRIDE + col) = make_float2(acc[mt][nt][2], acc[mt][nt][3]);
        }
    }
    __syncthreads();
}

// ---------------------------------------------------------------------------
// Conversion kernels (fp32 -> bf16)
// ---------------------------------------------------------------------------
__global__ void k_cvt_x(const float* __restrict__ x) {
    uint32_t* dst = (uint32_t*)g_xb;
    const int n4 = R_TOTAL * D_DIM / 4;
    for (int i = blockIdx.x * blockDim.x + threadIdx.x; i < n4; i += gridDim.x * blockDim.x) {
        float4 v = *(const float4*)(x + (size_t)i * 4);
        dst[i * 2]     = packbf(v.x, v.y);
        dst[i * 2 + 1] = packbf(v.z, v.w);
    }
}

__global__ void k_cvt_w(const float* __restrict__ Wq, const float* __restrict__ Wk,
                        const float* __restrict__ Wv, const float* __restrict__ Wo,
                        const float* __restrict__ W1, const float* __restrict__ W2) {
    const int n4 = (4 * 16384 + 2 * 32768) / 4;   // 32768
    for (int i = blockIdx.x * blockDim.x + threadIdx.x; i < n4; i += gridDim.x * blockDim.x) {
        const float* src;
        __nv_bfloat16* dst;
        int off;
        if      (i < 4096)  { src = Wq; dst = g_Wqb; off = i; }
        else if (i < 8192)  { src = Wk; dst = g_Wkb; off = i - 4096; }
        else if (i < 12288) { src = Wv; dst = g_Wvb; off = i - 8192; }
        else if (i < 16384) { src = Wo; dst = g_Wob; off = i - 12288; }
        else if (i < 24576) { src = W1; dst = g_W1b; off = i - 16384; }
        else                { src = W2; dst = g_W2b; off = i - 24576; }
        float4 v = *(const float4*)(src + (size_t)off * 4);
        uint32_t* d = (uint32_t*)dst + off * 2;
        d[0] = packbf(v.x, v.y);
        d[1] = packbf(v.z, v.w);
    }
}

// ---------------------------------------------------------------------------
// Kernel 1: QKV — resident A (x tile), streams Wq,Wk,Wv. grid 488, block 256.
// q output pre-scaled by QSCALE so attention uses raw exp2.
// ---------------------------------------------------------------------------
__global__ void __launch_bounds__(256) k_qkv(const float* __restrict__ bq,
                                             const float* __restrict__ bk,
                                             const float* __restrict__ bv) {
    extern __shared__ char sm[];
    const uint32_t smB = (uint32_t)__cvta_generic_to_shared(sm);
    const uint32_t aTile = smB;
    const uint32_t bst0 = smB + ATILE_BYTES;
    const int row0 = blockIdx.x << 7;

    const int tid  = threadIdx.x;
    const int warp = tid >> 5;
    const int lane = tid & 31;
    const int gid  = lane >> 2;
    const int tig  = lane & 3;
    const int wm   = warp >> 2;
    const int wn   = warp & 3;

    fill_A_tile(aTile, g_xb, row0);
    fill_Bchunk(bst0, g_Wqb, D_DIM, 0, 0);   // group0 = A + B(w0,ch0)

    float acc[4][4][4];
    #pragma unroll
    for (int i = 0; i < 4; i++)
        #pragma unroll
        for (int j = 0; j < 4; j++)
            #pragma unroll
            for (int r = 0; r < 4; r++) acc[i][j][r] = 0.f;

    for (int t = 0; t < 12; t++) {
        const int ch = t & 3, w = t >> 2;
        if (t + 1 < 12) {
            const int t1 = t + 1;
            const __nv_bfloat16* Bn = ((t1 >> 2) == 0) ? g_Wqb : ((t1 >> 2) == 1) ? g_Wkb : g_Wvb;
            fill_Bchunk(bst0 + ((t1 & 1) ? B_STAGE : 0), Bn, D_DIM, 0, (t1 & 3) << 5);
            cp_wait<1>();
        } else {
            cp_wait<0>();
        }
        __syncthreads();
        mma_chunk_resA(aTile, bst0 + ((t & 1) ? B_STAGE : 0), ch, acc, wm, wn, lane);
        __syncthreads();

        if (ch == 3) {
            const float* bias   = (w == 0) ? bq : (w == 1) ? bk : bv;
            __nv_bfloat16* out  = (w == 0) ? g_qb : (w == 1) ? g_kb : g_vb;
            const float scale   = (w == 0) ? QSCALE : 1.f;
            #pragma unroll
            for (int mt = 0; mt < 4; mt++) {
                int r0 = row0 + wm * 64 + mt * 16 + gid;
                int r1 = r0 + 8;
                #pragma unroll
                for (int nt = 0; nt < 4; nt++) {
                    int col = wn * 32 + nt * 8 + (tig << 1);
                    float b0 = bias[col], b1 = bias[col + 1];
                    if (r0 < R_TOTAL)
                        *(uint32_t*)(out + (size_t)r0 * D_DIM + col) =
                            packbf((acc[mt][nt][0] + b0) * scale, (acc[mt][nt][1] + b1) * scale);
                    if (r1 < R_TOTAL)
                        *(uint32_t*)(out + (size_t)r1 * D_DIM + col) =
                            packbf((acc[mt][nt][2] + b0) * scale, (acc[mt][nt][3] + b1) * scale);
                    acc[mt][nt][0] = acc[mt][nt][1] = acc[mt][nt][2] = acc[mt][nt][3] = 0.f;
                }
            }
        }
    }
}

// ---------------------------------------------------------------------------
// Kernel 2: attention per (b,h,t). grid = 1536, block = 256.
// exp2-only softmax (q pre-scaled); rowsum via ones-row MMA; ldmatrix frags.
// ---------------------------------------------------------------------------
__global__ void __launch_bounds__(256) attn_kernel() {
    __shared__ __align__(16) uint32_t Qs[NKP * 8];           // [336][16] bf16, stride 8 u32
    __shared__ __align__(16) uint32_t Ks[NKP * 12];          // stride 12 u32 (48B, ldsm-clean)
    __shared__ __align__(16) uint32_t Vt[24 * (VT_STRIDE/2)]; // rows 0-15 V^T, 16 ones, 17-23 zero

    const int bid = blockIdx.x;
    const int t = bid % TT;
    const int h = (bid / TT) % H_HEADS;
    const int b = bid / (TT * H_HEADS);
    const int row0 = (b * TT + t) * NN;
    const int hoff = h * HD;
    const int tid = threadIdx.x;

    __nv_bfloat16* Vtb = (__nv_bfloat16*)Vt;

    // Fill Q/K/V^T
    for (int idx = tid; idx < NKP * 2; idx += 256) {
        int m = idx >> 1;
        int seg = idx & 1;
        uint4 qv, kv, vv;
        if (m < NN) {
            size_t base = (size_t)(row0 + m) * D_DIM + hoff + seg * 8;
            qv = *(const uint4*)(g_qb + base);
            kv = *(const uint4*)(g_kb + base);
            vv = *(const uint4*)(g_vb + base);
        } else {
            qv = kv = vv = make_uint4(0, 0, 0, 0);
        }
        *(uint4*)(Qs + m * 8 + seg * 4) = qv;
        *(uint4*)(Ks + m * 12 + seg * 4) = kv;
        int d0 = seg * 8;
        uint32_t vu[4] = {vv.x, vv.y, vv.z, vv.w};
        #pragma unroll
        for (int j = 0; j < 4; j++) {
            __nv_bfloat162 p = *(__nv_bfloat162*)&vu[j];
            Vtb[(d0 + 2 * j)     * VT_STRIDE + m] = p.x;
            Vtb[(d0 + 2 * j + 1) * VT_STRIDE + m] = p.y;
        }
    }
    // Ones row (16) for m<NN, rows 17-23 zero
    for (int i = tid; i < 8 * (VT_STRIDE / 2); i += 256) {
        int r = 16 + i / (VT_STRIDE / 2);
        int cu = i % (VT_STRIDE / 2);
        int m = cu * 2;
        uint32_t val = 0;
        if (r == 16) {
            if (m + 1 < NN)      val = 0x3F803F80u;
            else if (m < NN)     val = 0x00003F80u;
        }
        Vt[(r) * (VT_STRIDE / 2) + cu] = val;
    }
    __syncthreads();

    const int warp = tid >> 5;
    const int lane = tid & 31;
    const int gid  = lane >> 2;
    const int tig  = lane & 3;

    // per-lane ldmatrix bases
    const int rowInTile = (lane & 7) + ((lane >> 4) << 3);
    const uint32_t off16 = (uint32_t)(lane & 8) << 1;          // 0 or 16
    const uint32_t ksSm = (uint32_t)__cvta_generic_to_shared(Ks);
    const uint32_t vtSm = (uint32_t)__cvta_generic_to_shared(Vt);
    const uint32_t kLane  = ksSm + (uint32_t)rowInTile * 48 + off16;
    const uint32_t vLane  = vtSm + (uint32_t)rowInTile * (VT_STRIDE * 2) + off16;
    const uint32_t v1Lane = vtSm + (uint32_t)(16 + (lane & 7)) * (VT_STRIDE * 2) + off16;

    for (int mt = warp; mt < 21; mt += 8) {
        const int m0 = mt << 4;
        uint32_t qa[4];
        qa[0] = Qs[(m0 + gid) * 8 + tig];
        qa[1] = Qs[(m0 + gid + 8) * 8 + tig];
        qa[2] = Qs[(m0 + gid) * 8 + tig + 4];
        qa[3] = Qs[(m0 + gid + 8) * 8 + tig + 4];

        float oc0[4] = {0.f, 0.f, 0.f, 0.f};
        float oc1[4] = {0.f, 0.f, 0.f, 0.f};
        float oc2[4] = {0.f, 0.f, 0.f, 0.f};   // rowsum via ones row

        for (int j = 0; j < 21; j++) {
            float c0[4] = {0.f, 0.f, 0.f, 0.f};
            float c1[4] = {0.f, 0.f, 0.f, 0.f};
            uint32_t kr[4];
            ldsm_x4(kr, kLane + (uint32_t)j * (16 * 48));
            mma_bf16(c0, qa, kr);        // uses kr[0],kr[1]
            mma_bf16(c1, qa, kr + 2);    // uses kr[2],kr[3]

            float p00 = ex2(c0[0]);
            float p01 = ex2(c0[1]);
            float p02 = ex2(c0[2]);
            float p03 = ex2(c0[3]);
            float p10 = ex2(c1[0]);
            float p11 = ex2(c1[1]);
            float p12 = ex2(c1[2]);
            float p13 = ex2(c1[3]);

            uint32_t pa[4];
            pa[0] = packbf(p00, p01);
            pa[1] = packbf(p02, p03);
            pa[2] = packbf(p10, p11);
            pa[3] = packbf(p12, p13);

            uint32_t vr[4], v1r[2];
            ldsm_x4(vr, vLane + (uint32_t)j * 32);
            ldsm_x2(v1r, v1Lane + (uint32_t)j * 32);
            mma_bf16(oc0, pa, vr);
            mma_bf16(oc1, pa, vr + 2);
            mma_bf16(oc2, pa, v1r);
        }

        // rowsum lives in ones column (col 0 of the extra tile) -> tig==0's c[0]/c[2]
        float rs0 = __shfl_sync(0xffffffffu, oc2[0], lane & ~3);
        float rs1 = __shfl_sync(0xffffffffu, oc2[2], lane & ~3);
        float i0 = 1.f / rs0;
        float i1 = 1.f / rs1;

        int r0 = m0 + gid;
        int r1 = m0 + gid + 8;
        if (r0 < NN) {
            __nv_bfloat16* op = g_attb + (size_t)(row0 + r0) * D_DIM + hoff;
            *(uint32_t*)(op + 2 * tig)     = packbf(oc0[0] * i0, oc0[1] * i0);
            *(uint32_t*)(op + 8 + 2 * tig) = packbf(oc1[0] * i0, oc1[1] * i0);
        }
        if (r1 < NN) {
            __nv_bfloat16* op = g_attb + (size_t)(row0 + r1) * D_DIM + hoff;
            *(uint32_t*)(op + 2 * tig)     = packbf(oc0[2] * i1, oc0[3] * i1);
            *(uint32_t*)(op + 8 + 2 * tig) = packbf(oc1[2] * i1, oc1[3] * i1);
        }
    }
}

// ---------------------------------------------------------------------------
// Kernel 3: h = LN1(x + att @ Wo + bo); writes g_h (fp32) + g_hb (bf16).
// ---------------------------------------------------------------------------
__global__ void __launch_bounds__(256) k_projo_ln1(const float* __restrict__ x,
                                                   const float* __restrict__ bo,
                                                   const float* __restrict__ g1, const float* __restrict__ b1) {
    extern __shared__ char sm[];
    float* smf = (float*)sm;
    const int row0 = blockIdx.x << 7;

    float acc[4][4][4];
    gemm_pipe(sm, g_attb, D_DIM, row0, g_Wob, D_DIM, 0, D_DIM, acc);
    stage_c(smf, acc);

    const int tid = threadIdx.x;
    if (tid < 128) {
        int row = row0 + tid;
        if (row < R_TOTAL) {
            const float* Cr = smf + tid * CS_STRIDE;
            const float* xr = x + (size_t)row * D_DIM;
            float s1 = 0.f, s2 = 0.f;
            #pragma unroll
            for (int c = 0; c < 128; c++) {
                float v = Cr[c] + bo[c] + xr[c];
                s1 += v; s2 += v * v;
            }
            float mean = s1 * (1.f / 128.f);
            float var  = s2 * (1.f / 128.f) - mean * mean;
            float rstd = rsqrtf(var + 1e-5f);
            float* hr = g_h + (size_t)row * D_DIM;
            uint32_t* hb = (uint32_t*)(g_hb + (size_t)row * D_DIM);
            #pragma unroll
            for (int c = 0; c < 128; c += 4) {
                float4 o;
                o.x = (Cr[c]     + bo[c]     + xr[c]     - mean) * rstd * g1[c]     + b1[c];
                o.y = (Cr[c + 1] + bo[c + 1] + xr[c + 1] - mean) * rstd * g1[c + 1] + b1[c + 1];
                o.z = (Cr[c + 2] + bo[c + 2] + xr[c + 2] - mean) * rstd * g1[c + 2] + b1[c + 2];
                o.w = (Cr[c + 3] + bo[c + 3] + xr[c + 3] - mean) * rstd * g1[c + 3] + b1[c + 3];
                *(float4*)(hr + c) = o;
                hb[c >> 1]       = packbf(o.x, o.y);
                hb[(c >> 1) + 1] = packbf(o.z, o.w);
            }
        }
    }
}

// ---------------------------------------------------------------------------
// Kernel 4: mid = gelu(h @ W1 + b1) — resident A, two N-halves. grid 488.
// ---------------------------------------------------------------------------
__global__ void __launch_bounds__(256) k_ffn1(const float* __restrict__ b1) {
    extern __shared__ char sm[];
    const uint32_t smB = (uint32_t)__cvta_generic_to_shared(sm);
    const uint32_t aTile = smB;
    const uint32_t bst0 = smB + ATILE_BYTES;
    const int row0 = blockIdx.x << 7;

    const int tid  = threadIdx.x;
    const int warp = tid >> 5;
    const int lane = tid & 31;
    const int gid  = lane >> 2;
    const int tig  = lane & 3;
    const int wm   = warp >> 2;
    const int wn   = warp & 3;

    fill_A_tile(aTile, g_hb, row0);
    fill_Bchunk(bst0, g_W1b, F_DIM, 0, 0);

    float acc[4][4][4];
    #pragma unroll
    for (int i = 0; i < 4; i++)
        #pragma unroll
        for (int j = 0; j < 4; j++)
            #pragma unroll
            for (int r = 0; r < 4; r++) acc[i][j][r] = 0.f;

    for (int t = 0; t < 8; t++) {
        const int ch = t & 3, w = t >> 2;
        if (t + 1 < 8) {
            const int t1 = t + 1;
            fill_Bchunk(bst0 + ((t1 & 1) ? B_STAGE : 0), g_W1b, F_DIM,
                        (t1 >> 2) << 7, (t1 & 3) << 5);
            cp_wait<1>();
        } else {
            cp_wait<0>();
        }
        __syncthreads();
        mma_chunk_resA(aTile, bst0 + ((t & 1) ? B_STAGE : 0), ch, acc, wm, wn, lane);
        __syncthreads();

        if (ch == 3) {
            const int col0 = w << 7;
            #pragma unroll
            for (int mt = 0; mt < 4; mt++) {
                int r0 = row0 + wm * 64 + mt * 16 + gid;
                int r1 = r0 + 8;
                #pragma unroll
                for (int nt = 0; nt < 4; nt++) {
                    int col = col0 + wn * 32 + nt * 8 + (tig << 1);
                    float b0 = b1[col], bb1 = b1[col + 1];
                    float v0 = acc[mt][nt][0] + b0;
                    float v1 = acc[mt][nt][1] + bb1;
                    float v2 = acc[mt][nt][2] + b0;
                    float v3 = acc[mt][nt][3] + bb1;
                    float e0 = 0.5f * v0 * (1.f + erff(v0 * 0.70710678118654752f));
                    float e1 = 0.5f * v1 * (1.f + erff(v1 * 0.70710678118654752f));
                    float e2 = 0.5f * v2 * (1.f + erff(v2 * 0.70710678118654752f));
                    float e3 = 0.5f * v3 * (1.f + erff(v3 * 0.70710678118654752f));
                    if (r0 < R_TOTAL)
                        *(uint32_t*)(g_midb + (size_t)r0 * F_DIM + col) = packbf(e0, e1);
                    if (r1 < R_TOTAL)
                        *(uint32_t*)(g_midb + (size_t)r1 * F_DIM + col) = packbf(e2, e3);
                    acc[mt][nt][0] = acc[mt][nt][1] = acc[mt][nt][2] = acc[mt][nt][3] = 0.f;
                }
            }
        }
    }
}

// ---------------------------------------------------------------------------
// Kernel 5: out = LN2(h + mid @ W2 + b2). grid 488, block 256. K=256.
// ---------------------------------------------------------------------------
__global__ void __launch_bounds__(256) k_ffn2_ln2(const float* __restrict__ b2,
                                                  const float* __restrict__ g2,
                                                  const float* __restrict__ bt2,
                                                  float* __restrict__ out) {
    extern __shared__ char sm[];
    float* smf = (float*)sm;
    const int row0 = blockIdx.x << 7;

    float acc[4][4][4];
    gemm_pipe(sm, g_midb, F_DIM, row0, g_W2b, D_DIM, 0, F_DIM, acc);
    stage_c(smf, acc);

    const int tid = threadIdx.x;
    if (tid < 128) {
        int row = row0 + tid;
        if (row < R_TOTAL) {
            const float* Cr = smf + tid * CS_STRIDE;
            const float* hr = g_h + (size_t)row * D_DIM;
            float s1 = 0.f, s2 = 0.f;
            #pragma unroll
            for (int c = 0; c < 128; c++) {
                float v = Cr[c] + b2[c] + hr[c];
                s1 += v; s2 += v * v;
            }
            float mean = s1 * (1.f / 128.f);
            float var  = s2 * (1.f / 128.f) - mean * mean;
            float rstd = rsqrtf(var + 1e-5f);
            float* orow = out + (size_t)row * D_DIM;
            #pragma unroll
            for (int c = 0; c < 128; c += 4) {
                float4 o;
                o.x = (Cr[c]     + b2[c]     + hr[c]     - mean) * rstd * g2[c]     + bt2[c];
                o.y = (Cr[c + 1] + b2[c + 1] + hr[c + 1] - mean) * rstd * g2[c + 1] + bt2[c + 1];
                o.z = (Cr[c + 2] + b2[c + 2] + hr[c + 2] - mean) * rstd * g2[c + 2] + bt2[c + 2];
                o.w = (Cr[c + 3] + b2[c + 3] + hr[c + 3] - mean) * rstd * g2[c + 3] + bt2[c + 3];
                *(float4*)(orow + c) = o;
            }
        }
    }
}

// ---------------------------------------------------------------------------
extern "C" void kernel_launch(void* const* d_in, const int* in_sizes, int n_in,
                              void* d_out, int out_size) {
    const float* x     = (const float*)d_in[0];
    const float* Wq    = (const float*)d_in[1];
    const float* bq    = (const float*)d_in[2];
    const float* Wk    = (const float*)d_in[3];
    const float* bk    = (const float*)d_in[4];
    const float* Wv    = (const float*)d_in[5];
    const float* bv    = (const float*)d_in[6];
    const float* Wo    = (const float*)d_in[7];
    const float* bo    = (const float*)d_in[8];
    const float* ln1_g = (const float*)d_in[9];
    const float* ln1_b = (const float*)d_in[10];
    const float* W1    = (const float*)d_in[11];
    const float* b1    = (const float*)d_in[12];
    const float* W2    = (const float*)d_in[13];
    const float* b2    = (const float*)d_in[14];
    const float* ln2_g = (const float*)d_in[15];
    const float* ln2_b = (const float*)d_in[16];
    float* out = (float*)d_out;

    cudaFuncSetAttribute(k_qkv,       cudaFuncAttributeMaxDynamicSharedMemorySize, MP_SMEM);
    cudaFuncSetAttribute(k_ffn1,      cudaFuncAttributeMaxDynamicSharedMemorySize, MP_SMEM);
    cudaFuncSetAttribute(k_projo_ln1, cudaFuncAttributeMaxDynamicSharedMemorySize, LN_SMEM);
    cudaFuncSetAttribute(k_ffn2_ln2,  cudaFuncAttributeMaxDynamicSharedMemorySize, LN_SMEM);

    k_cvt_w<<<64, 512>>>(Wq, Wk, Wv, Wo, W1, W2);
    k_cvt_x<<<1024, 512>>>(x);
    k_qkv<<<M_TILES, 256, MP_SMEM>>>(bq, bk, bv);
    attn_kernel<<<NB * H_HEADS * TT, 256>>>();
    k_projo_ln1<<<M_TILES, 256, LN_SMEM>>>(x, bo, ln1_g, ln1_b);
    k_ffn1<<<M_TILES, 256, MP_SMEM>>>(b1);
    k_ffn2_ln2<<<M_TILES, 256, LN_SMEM>>>(b2, ln2_g, ln2_b, out);
}